// round 11
// baseline (speedup 1.0000x reference)
#include <cuda_runtime.h>
#include <cuda_bf16.h>
#include <cuda_fp16.h>
#include <cstdint>

#define NN 50000
#define NE 800000
#define NE2 850000   /* NE + NN self loops */
#define NG 64

// ---------------- device scratch (no allocations allowed) ----------------
__device__ __align__(16) __half g_h16[NN * 256]; // per-layer h = x@W  [N, H*C] fp16
__device__ __align__(16) __nv_bfloat16 g_xhi[(size_t)NN * 128]; // activation hi (stride=K)
__device__ __align__(16) __nv_bfloat16 g_xlo[(size_t)NN * 128]; // activation lo
__device__ __align__(16) float g_als[NN * 4];
__device__ __align__(16) float g_ald[NN * 4];
__device__ __align__(16) float g_alpha[NE2 * 4]; // overflow fallback only
__device__ __align__(16) __nv_bfloat16 g_bthi[3 * 256 * 128]; // W^T split hi, per layer
__device__ __align__(16) __nv_bfloat16 g_btlo[3 * 256 * 128]; // W^T split lo, per layer
__device__ int   g_deg[NN];
__device__ int   g_offs[NN + 1];
__device__ int   g_cursor[NN];
__device__ int   g_ssrc[NE2];
__device__ float g_psum[NG * 64];
__device__ float g_pcnt[NG];

// ---------------- CSR build ----------------
__global__ void k_init() {
  int i = blockIdx.x * blockDim.x + threadIdx.x;
  if (i < NN) g_deg[i] = 1;              // self-loop pre-counted
  if (i < NG * 64) g_psum[i] = 0.f;
  if (i < NG) g_pcnt[i] = 0.f;
}

__global__ void k_degree(const int* __restrict__ ei) {
  int e = blockIdx.x * blockDim.x + threadIdx.x;
  if (e < NE) atomicAdd(&g_deg[ei[NE + e]], 1);
}

__global__ void k_scan() {
  __shared__ int sums[1024];
  const int CH = (NN + 1023) / 1024;   // 49
  int t = threadIdx.x;
  int base = t * CH;
  int s = 0;
  for (int i = 0; i < CH; i++) { int idx = base + i; if (idx < NN) s += g_deg[idx]; }
  sums[t] = s;
  __syncthreads();
  for (int off = 1; off < 1024; off <<= 1) {
    int v = (t >= off) ? sums[t - off] : 0;
    __syncthreads();
    sums[t] += v;
    __syncthreads();
  }
  int run = (t == 0) ? 0 : sums[t - 1];
  for (int i = 0; i < CH; i++) {
    int idx = base + i;
    if (idx < NN) { g_offs[idx] = run; g_cursor[idx] = run; run += g_deg[idx]; }
  }
  if (t == 0) g_offs[NN] = sums[1023];
}

__global__ void k_scatter(const int* __restrict__ ei) {
  int e = blockIdx.x * blockDim.x + threadIdx.x;
  if (e >= NE2) return;
  int s, d;
  if (e < NE) { s = ei[e]; d = ei[NE + e]; }
  else        { s = e - NE; d = s; }
  int pos = atomicAdd(&g_cursor[d], 1);
  g_ssrc[pos] = s;
}

// ---------------- x fp32 -> split bf16 hi/lo (layer-1 input) ----------------
__global__ void k_xsplit(const float* __restrict__ x) {
  int i = blockIdx.x * blockDim.x + threadIdx.x;
  if (i >= NN * 128) return;
  float v = x[i];
  __nv_bfloat16 hi = __float2bfloat16(v);
  g_xhi[i] = hi;
  g_xlo[i] = __float2bfloat16(v - __bfloat162float(hi));
}

// ---------------- W split+transpose: W[K][256] fp32 -> slab [256][K] bf16 ----
__global__ void k_bsplit(const float* __restrict__ W, int K, int layer) {
  int idx = blockIdx.x * blockDim.x + threadIdx.x;
  if (idx >= 256 * K) return;
  int n = idx / K, k = idx - n * K;
  float v = W[k * 256 + n];
  __nv_bfloat16 hi = __float2bfloat16(v);
  __nv_bfloat16 lo = __float2bfloat16(v - __bfloat162float(hi));
  g_bthi[layer * 32768 + idx] = hi;
  g_btlo[layer * 32768 + idx] = lo;
}

// ---------------- tensor-core GEMM + fused attention logits ----------------
__device__ __forceinline__ void mma_bf16(float* c, const uint32_t* a, uint32_t b0, uint32_t b1) {
  asm volatile(
      "mma.sync.aligned.m16n8k16.row.col.f32.bf16.bf16.f32 "
      "{%0,%1,%2,%3}, {%4,%5,%6,%7}, {%8,%9}, {%0,%1,%2,%3};\n"
      : "+f"(c[0]), "+f"(c[1]), "+f"(c[2]), "+f"(c[3])
      : "r"(a[0]), "r"(a[1]), "r"(a[2]), "r"(a[3]), "r"(b0), "r"(b1));
}

__device__ __forceinline__ void ldsm4(uint32_t& r0, uint32_t& r1, uint32_t& r2, uint32_t& r3,
                                      uint32_t addr) {
  asm volatile("ldmatrix.sync.aligned.m8n8.x4.shared.b16 {%0,%1,%2,%3}, [%4];"
               : "=r"(r0), "=r"(r1), "=r"(r2), "=r"(r3) : "r"(addr));
}

#define CPA(dst, src, sz) \
  asm volatile("cp.async.cg.shared.global [%0], [%1], 16, %2;" ::"r"(dst), "l"(src), "r"(sz))

#define SSTR 40
// dynamic smem: 2 buffers x 4 regions x (128*SSTR) bf16
#define REG_BYTES (128 * SSTR * 2)          /* 10240 */
#define BUF_BYTES (4 * REG_BYTES)           /* 40960 */
#define SMEM_DYN  (2 * BUF_BYTES)           /* 81920 */

__global__ void __launch_bounds__(256, 2)
k_gemm_mma(int K, const float* __restrict__ as_, const float* __restrict__ ad_, int layer) {
  extern __shared__ __nv_bfloat16 smd[];
  const __nv_bfloat16* Bhi = g_bthi + layer * 32768;
  const __nv_bfloat16* Blo = g_btlo + layer * 32768;

  const int bm = blockIdx.y * 128;
  const int bn = blockIdx.x * 128;
  const int tid = threadIdx.x;
  const int warp = tid >> 5, lane = tid & 31;
  const int wm = warp >> 1, wn = warp & 1;     // 4x2 warp grid
  const int gid = lane >> 2, tig = lane & 3;

  // ldmatrix lane-address components
  const int lt = lane >> 3, lr = lane & 7;
  const int a_row = (lt & 1) * 8 + lr;
  const int a_col = (lt >> 1) * 8;
  const int b_row = (lt >> 1) * 8 + lr;
  const int b_col = (lt & 1) * 8;

  const uint32_t u0 = (uint32_t)__cvta_generic_to_shared(smd);

  // staging coordinates: row = tid>>2, col16 = (tid&3)*8
  const int st_r0 = tid >> 2, st_c = (tid & 3) * 8;
  const int st_r1 = st_r0 + 64;
  const uint32_t sdo0 = (uint32_t)((st_r0 * SSTR + st_c) * 2);
  const uint32_t sdo1 = (uint32_t)((st_r1 * SSTR + st_c) * 2);

  const int nc = K >> 5;

  auto stage = [&](int c) {
    uint32_t ub = u0 + (uint32_t)(c & 1) * BUF_BYTES;
    int k0 = c * 32;
    int gr0 = bm + st_r0, gr1 = bm + st_r1;
    int sz0 = (gr0 < NN) ? 16 : 0, sz1 = (gr1 < NN) ? 16 : 0;
    size_t so0 = (size_t)(gr0 < NN ? gr0 : 0) * K + k0 + st_c;
    size_t so1 = (size_t)(gr1 < NN ? gr1 : 0) * K + k0 + st_c;
    CPA(ub + sdo0, g_xhi + so0, sz0);
    CPA(ub + REG_BYTES + sdo0, g_xlo + so0, sz0);
    CPA(ub + sdo1, g_xhi + so1, sz1);
    CPA(ub + REG_BYTES + sdo1, g_xlo + so1, sz1);
    size_t bo0 = (size_t)(bn + st_r0) * K + k0 + st_c;
    size_t bo1 = (size_t)(bn + st_r1) * K + k0 + st_c;
    CPA(ub + 2 * REG_BYTES + sdo0, Bhi + bo0, 16);
    CPA(ub + 3 * REG_BYTES + sdo0, Blo + bo0, 16);
    CPA(ub + 2 * REG_BYTES + sdo1, Bhi + bo1, 16);
    CPA(ub + 3 * REG_BYTES + sdo1, Blo + bo1, 16);
    asm volatile("cp.async.commit_group;");
  };

  float acc[2][8][4];
#pragma unroll
  for (int i = 0; i < 2; i++)
#pragma unroll
    for (int j = 0; j < 8; j++)
#pragma unroll
      for (int q = 0; q < 4; q++) acc[i][j][q] = 0.f;

  stage(0);
  for (int c = 0; c < nc; c++) {
    if (c + 1 < nc) {
      stage(c + 1);
      asm volatile("cp.async.wait_group 1;");
    } else {
      asm volatile("cp.async.wait_group 0;");
    }
    __syncthreads();

    const uint32_t ub = u0 + (uint32_t)(c & 1) * BUF_BYTES;
    const uint32_t uAhi = ub, uAlo = ub + REG_BYTES;
    const uint32_t uBhi = ub + 2 * REG_BYTES, uBlo = ub + 3 * REG_BYTES;

#pragma unroll
    for (int ks = 0; ks < 2; ks++) {
      const int kb = ks * 16;
      uint32_t ahi[2][4], alo[2][4];
#pragma unroll
      for (int i = 0; i < 2; i++) {
        uint32_t off = (uint32_t)(((wm * 32 + i * 16 + a_row) * SSTR + kb + a_col) * 2);
        ldsm4(ahi[i][0], ahi[i][1], ahi[i][2], ahi[i][3], uAhi + off);
        ldsm4(alo[i][0], alo[i][1], alo[i][2], alo[i][3], uAlo + off);
      }
#pragma unroll
      for (int jj = 0; jj < 4; jj++) {
        uint32_t off = (uint32_t)(((wn * 64 + jj * 16 + b_row) * SSTR + kb + b_col) * 2);
        uint32_t bh0, bh1, bh2, bh3, bl0, bl1, bl2, bl3;
        ldsm4(bh0, bh1, bh2, bh3, uBhi + off);
        ldsm4(bl0, bl1, bl2, bl3, uBlo + off);
#pragma unroll
        for (int i = 0; i < 2; i++) {
          mma_bf16(acc[i][jj * 2],     ahi[i], bh0, bh1);
          mma_bf16(acc[i][jj * 2],     ahi[i], bl0, bl1);
          mma_bf16(acc[i][jj * 2],     alo[i], bh0, bh1);
          mma_bf16(acc[i][jj * 2 + 1], ahi[i], bh2, bh3);
          mma_bf16(acc[i][jj * 2 + 1], ahi[i], bl2, bl3);
          mma_bf16(acc[i][jj * 2 + 1], alo[i], bh2, bh3);
        }
      }
    }
    __syncthreads();
  }

  // --- epilogue 1: write fp16 h
#pragma unroll
  for (int i = 0; i < 2; i++) {
#pragma unroll
    for (int j = 0; j < 8; j++) {
      int row = bm + wm * 32 + i * 16 + gid;
      int col = bn + wn * 64 + j * 8 + 2 * tig;
      __half2 p01 = __floats2half2_rn(acc[i][j][0], acc[i][j][1]);
      __half2 p23 = __floats2half2_rn(acc[i][j][2], acc[i][j][3]);
      if (row < NN)
        *(__half2*)(g_h16 + (size_t)row * 256 + col) = p01;
      if (row + 8 < NN)
        *(__half2*)(g_h16 + (size_t)(row + 8) * 256 + col) = p23;
    }
  }

  // --- epilogue 2: fused attention logits for head = 2*bn + wn
  {
    const int head = blockIdx.x * 2 + wn;
    float wa[16], wd[16];
#pragma unroll
    for (int j = 0; j < 8; j++) {
      int c = j * 8 + 2 * tig;
      wa[j * 2 + 0] = as_[head * 64 + c];
      wa[j * 2 + 1] = as_[head * 64 + c + 1];
      wd[j * 2 + 0] = ad_[head * 64 + c];
      wd[j * 2 + 1] = ad_[head * 64 + c + 1];
    }
#pragma unroll
    for (int i = 0; i < 2; i++) {
      float s0 = 0.f, s1 = 0.f, d0 = 0.f, d1 = 0.f;
#pragma unroll
      for (int j = 0; j < 8; j++) {
        s0 = fmaf(acc[i][j][0], wa[j * 2], fmaf(acc[i][j][1], wa[j * 2 + 1], s0));
        s1 = fmaf(acc[i][j][2], wa[j * 2], fmaf(acc[i][j][3], wa[j * 2 + 1], s1));
        d0 = fmaf(acc[i][j][0], wd[j * 2], fmaf(acc[i][j][1], wd[j * 2 + 1], d0));
        d1 = fmaf(acc[i][j][2], wd[j * 2], fmaf(acc[i][j][3], wd[j * 2 + 1], d1));
      }
#pragma unroll
      for (int o = 1; o <= 2; o <<= 1) {
        s0 += __shfl_xor_sync(0xffffffffu, s0, o);
        s1 += __shfl_xor_sync(0xffffffffu, s1, o);
        d0 += __shfl_xor_sync(0xffffffffu, d0, o);
        d1 += __shfl_xor_sync(0xffffffffu, d1, o);
      }
      if (tig == 0) {
        int row = bm + wm * 32 + i * 16 + gid;
        if (row < NN)     { g_als[row * 4 + head] = s0; g_ald[row * 4 + head] = d0; }
        if (row + 8 < NN) { g_als[(row + 8) * 4 + head] = s1; g_ald[(row + 8) * 4 + head] = d1; }
      }
    }
  }
}

// ---------------- softmax + aggregation: one warp per dst node ----------------
// Max-shift skipped: logits are O(1) by construction -> exp cannot overflow.
// Per-edge alpha cached in shared memory (gmem fallback for deg > 64).
__device__ __forceinline__ float leaky(float v) { return v >= 0.f ? v : 0.2f * v; }

#define ACAP 64

__global__ void __launch_bounds__(256)
k_agg(const float* __restrict__ bias, float* __restrict__ emb, int final_) {
  __shared__ float4 s_alpha[8][ACAP];
  int warp = (blockIdx.x * blockDim.x + threadIdx.x) >> 5;
  int wip = threadIdx.x >> 5;
  int lane = threadIdx.x & 31;
  if (warp >= NN) return;
  const int n = warp;
  const int beg = g_offs[n], end = g_offs[n + 1];

  const float4 ald = *(const float4*)&g_ald[n * 4];

  float d0 = 0.f, d1 = 0.f, d2 = 0.f, d3 = 0.f;
  for (int e = beg + lane; e < end; e += 32) {
    int s = g_ssrc[e];
    float4 als = *(const float4*)&g_als[s * 4];
    float p0 = __expf(leaky(als.x + ald.x));
    float p1 = __expf(leaky(als.y + ald.y));
    float p2 = __expf(leaky(als.z + ald.z));
    float p3 = __expf(leaky(als.w + ald.w));
    d0 += p0; d1 += p1; d2 += p2; d3 += p3;
    int idx = e - beg;
    float4 pv = make_float4(p0, p1, p2, p3);
    if (idx < ACAP) s_alpha[wip][idx] = pv;
    else            *(float4*)&g_alpha[(size_t)e * 4] = pv;
  }
#pragma unroll
  for (int o = 16; o; o >>= 1) {
    d0 += __shfl_xor_sync(0xffffffffu, d0, o);
    d1 += __shfl_xor_sync(0xffffffffu, d1, o);
    d2 += __shfl_xor_sync(0xffffffffu, d2, o);
    d3 += __shfl_xor_sync(0xffffffffu, d3, o);
  }
  __syncwarp();

  const bool hs = (lane & 16) != 0;
  const float rA = 1.0f / (hs ? d1 : d0);
  const float rB = 1.0f / (hs ? d3 : d2);

  // phase B: warp-serial over edges (unroll 4); lanes cover 256 feats.
  float4 acc0 = make_float4(0.f, 0.f, 0.f, 0.f);
  float4 acc1 = make_float4(0.f, 0.f, 0.f, 0.f);
  const int deg = end - beg;
  int idx = 0;
  for (; idx + 3 < deg; idx += 4) {
    int s[4]; float4 p[4]; uint2 r0[4], r1[4];
#pragma unroll
    for (int j = 0; j < 4; j++) s[j] = g_ssrc[beg + idx + j];
#pragma unroll
    for (int j = 0; j < 4; j++)
      p[j] = (idx + j < ACAP) ? s_alpha[wip][idx + j]
                              : *(const float4*)&g_alpha[(size_t)(beg + idx + j) * 4];
#pragma unroll
    for (int j = 0; j < 4; j++) {
      const uint2* hp = (const uint2*)(g_h16 + (size_t)s[j] * 256);
      r0[j] = __ldg(hp + lane);
      r1[j] = __ldg(hp + 32 + lane);
    }
#pragma unroll
    for (int j = 0; j < 4; j++) {
      float a0 = (hs ? p[j].y : p[j].x) * rA;
      float a1 = (hs ? p[j].w : p[j].z) * rB;
      float2 f;
      f = __half22float2(*(const __half2*)&r0[j].x); acc0.x = fmaf(f.x, a0, acc0.x); acc0.y = fmaf(f.y, a0, acc0.y);
      f = __half22float2(*(const __half2*)&r0[j].y); acc0.z = fmaf(f.x, a0, acc0.z); acc0.w = fmaf(f.y, a0, acc0.w);
      f = __half22float2(*(const __half2*)&r1[j].x); acc1.x = fmaf(f.x, a1, acc1.x); acc1.y = fmaf(f.y, a1, acc1.y);
      f = __half22float2(*(const __half2*)&r1[j].y); acc1.z = fmaf(f.x, a1, acc1.z); acc1.w = fmaf(f.y, a1, acc1.w);
    }
  }
  for (; idx < deg; ++idx) {
    int s = g_ssrc[beg + idx];
    float4 p = (idx < ACAP) ? s_alpha[wip][idx] : *(const float4*)&g_alpha[(size_t)(beg + idx) * 4];
    float a0 = (hs ? p.y : p.x) * rA;
    float a1 = (hs ? p.w : p.z) * rB;
    const uint2* hp = (const uint2*)(g_h16 + (size_t)s * 256);
    uint2 r0 = __ldg(hp + lane);
    uint2 r1 = __ldg(hp + 32 + lane);
    float2 f;
    f = __half22float2(*(const __half2*)&r0.x); acc0.x = fmaf(f.x, a0, acc0.x); acc0.y = fmaf(f.y, a0, acc0.y);
    f = __half22float2(*(const __half2*)&r0.y); acc0.z = fmaf(f.x, a0, acc0.z); acc0.w = fmaf(f.y, a0, acc0.w);
    f = __half22float2(*(const __half2*)&r1.x); acc1.x = fmaf(f.x, a1, acc1.x); acc1.y = fmaf(f.y, a1, acc1.y);
    f = __half22float2(*(const __half2*)&r1.y); acc1.z = fmaf(f.x, a1, acc1.z); acc1.w = fmaf(f.y, a1, acc1.w);
  }

  float4 t;
  t.x = acc0.x + acc1.x; t.y = acc0.y + acc1.y;
  t.z = acc0.z + acc1.z; t.w = acc0.w + acc1.w;
  t.x += __shfl_xor_sync(0xffffffffu, t.x, 16);
  t.y += __shfl_xor_sync(0xffffffffu, t.y, 16);
  t.z += __shfl_xor_sync(0xffffffffu, t.z, 16);
  t.w += __shfl_xor_sync(0xffffffffu, t.w, 16);
  if (lane < 16) {
    const float4 b4 = *(const float4*)(bias + lane * 4);
    float ox = t.x * 0.25f + b4.x;
    float oy = t.y * 0.25f + b4.y;
    float oz = t.z * 0.25f + b4.z;
    float ow = t.w * 0.25f + b4.w;
    if (final_) {
      *(float4*)(emb + (size_t)n * 64 + lane * 4) = make_float4(ox, oy, oz, ow);
    } else {
      ox = fmaxf(ox, 0.f); oy = fmaxf(oy, 0.f);
      oz = fmaxf(oz, 0.f); ow = fmaxf(ow, 0.f);
      // split to bf16 hi/lo for the next GEMM's cp.async staging (stride 64)
      __nv_bfloat16 hx = __float2bfloat16(ox), hy = __float2bfloat16(oy);
      __nv_bfloat16 hz = __float2bfloat16(oz), hw = __float2bfloat16(ow);
      __nv_bfloat16 lx = __float2bfloat16(ox - __bfloat162float(hx));
      __nv_bfloat16 ly = __float2bfloat16(oy - __bfloat162float(hy));
      __nv_bfloat16 lz = __float2bfloat16(oz - __bfloat162float(hz));
      __nv_bfloat16 lw = __float2bfloat16(ow - __bfloat162float(hw));
      uint2 hv, lv;
      *(__nv_bfloat162*)&hv.x = __nv_bfloat162(hx, hy);
      *(__nv_bfloat162*)&hv.y = __nv_bfloat162(hz, hw);
      *(__nv_bfloat162*)&lv.x = __nv_bfloat162(lx, ly);
      *(__nv_bfloat162*)&lv.y = __nv_bfloat162(lz, lw);
      *(uint2*)(g_xhi + (size_t)n * 64 + lane * 4) = hv;
      *(uint2*)(g_xlo + (size_t)n * 64 + lane * 4) = lv;
    }
  }
}

// ---------------- node MLP heads + pooling ----------------
__device__ __forceinline__ float sigmoidf_(float x) { return 1.0f / (1.0f + __expf(-x)); }

__global__ void k_node_mlp(const float* __restrict__ emb, const int* __restrict__ batch,
                           const float* __restrict__ aw1, const float* __restrict__ ab1,
                           const float* __restrict__ aw2, const float* __restrict__ ab2,
                           const float* __restrict__ rw1, const float* __restrict__ rb1,
                           const float* __restrict__ rw2, const float* __restrict__ rb2,
                           const float* __restrict__ cw1, const float* __restrict__ cb1,
                           const float* __restrict__ cw2, const float* __restrict__ cb2,
                           float* __restrict__ anomaly, float* __restrict__ risk,
                           float* __restrict__ resource) {
  int warp = (blockIdx.x * blockDim.x + threadIdx.x) >> 5;
  int lane = threadIdx.x & 31;
  if (warp >= NN) return;
  int n = warp;
  float e0 = emb[(size_t)n * 64 + lane];
  float e1 = emb[(size_t)n * 64 + 32 + lane];

  float ha = ab1[lane], hr = rb1[lane], hc = cb1[lane];
#pragma unroll
  for (int k = 0; k < 32; k++) {
    float ek = __shfl_sync(0xffffffffu, e0, k);
    ha = fmaf(ek, aw1[k * 32 + lane], ha);
    hr = fmaf(ek, rw1[k * 32 + lane], hr);
    hc = fmaf(ek, cw1[k * 32 + lane], hc);
  }
#pragma unroll
  for (int k = 0; k < 32; k++) {
    float ek = __shfl_sync(0xffffffffu, e1, k);
    ha = fmaf(ek, aw1[(k + 32) * 32 + lane], ha);
    hr = fmaf(ek, rw1[(k + 32) * 32 + lane], hr);
    hc = fmaf(ek, cw1[(k + 32) * 32 + lane], hc);
  }
  ha = fmaxf(ha, 0.f); hr = fmaxf(hr, 0.f); hc = fmaxf(hc, 0.f);

  float va = ha * aw2[lane];
  float vr = hr * rw2[lane];
#pragma unroll
  for (int o = 16; o; o >>= 1) {
    va += __shfl_xor_sync(0xffffffffu, va, o);
    vr += __shfl_xor_sync(0xffffffffu, vr, o);
  }
  if (lane == 0) {
    anomaly[n] = sigmoidf_(va + ab2[0]);
    risk[n]    = sigmoidf_(vr + rb2[0]);
  }
#pragma unroll
  for (int o5 = 0; o5 < 5; o5++) {
    float vc = hc * cw2[lane * 5 + o5];
#pragma unroll
    for (int o = 16; o; o >>= 1) vc += __shfl_xor_sync(0xffffffffu, vc, o);
    if (lane == 0) resource[(size_t)n * 5 + o5] = vc + cb2[o5];
  }

  int g = batch[n];
  atomicAdd(&g_psum[g * 64 + lane], e0);
  atomicAdd(&g_psum[g * 64 + 32 + lane], e1);
  if (lane == 0) atomicAdd(&g_pcnt[g], 1.0f);
}

__global__ void k_graph_head(const float* __restrict__ gw1, const float* __restrict__ gb1,
                             const float* __restrict__ gw2, const float* __restrict__ gb2,
                             float* __restrict__ glog) {
  int g = blockIdx.x;
  int lane = threadIdx.x;
  float rc = 1.0f / fmaxf(g_pcnt[g], 1.0f);
  float hid = gb1[lane];
#pragma unroll
  for (int c = 0; c < 64; c++)
    hid = fmaf(g_psum[g * 64 + c] * rc, gw1[c * 32 + lane], hid);
  hid = fmaxf(hid, 0.f);
#pragma unroll
  for (int o4 = 0; o4 < 4; o4++) {
    float v = hid * gw2[lane * 4 + o4];
#pragma unroll
    for (int o = 16; o; o >>= 1) v += __shfl_xor_sync(0xffffffffu, v, o);
    if (lane == 0) glog[g * 4 + o4] = v + gb2[o4];
  }
}

// ---------------- launch ----------------
extern "C" void kernel_launch(void* const* d_in, const int* in_sizes, int n_in,
                              void* d_out, int out_size) {
  const float* x    = (const float*)d_in[0];
  const int*   ei   = (const int*)d_in[1];
  const int*   batch= (const int*)d_in[2];
  const float* W1   = (const float*)d_in[3];
  const float* as1  = (const float*)d_in[4];
  const float* ad1  = (const float*)d_in[5];
  const float* b1   = (const float*)d_in[6];
  const float* W2   = (const float*)d_in[7];
  const float* as2  = (const float*)d_in[8];
  const float* ad2  = (const float*)d_in[9];
  const float* b2   = (const float*)d_in[10];
  const float* W3   = (const float*)d_in[11];
  const float* as3  = (const float*)d_in[12];
  const float* ad3  = (const float*)d_in[13];
  const float* b3   = (const float*)d_in[14];
  const float* aw1  = (const float*)d_in[15];
  const float* ab1  = (const float*)d_in[16];
  const float* aw2  = (const float*)d_in[17];
  const float* ab2  = (const float*)d_in[18];
  const float* rw1  = (const float*)d_in[19];
  const float* rb1  = (const float*)d_in[20];
  const float* rw2  = (const float*)d_in[21];
  const float* rb2  = (const float*)d_in[22];
  const float* cw1  = (const float*)d_in[23];
  const float* cb1  = (const float*)d_in[24];
  const float* cw2  = (const float*)d_in[25];
  const float* cb2  = (const float*)d_in[26];
  const float* gw1  = (const float*)d_in[27];
  const float* gb1  = (const float*)d_in[28];
  const float* gw2  = (const float*)d_in[29];
  const float* gb2  = (const float*)d_in[30];

  float* out      = (float*)d_out;
  float* emb      = out;                        // N*64
  float* anomaly  = out + (size_t)NN * 64;      // N
  float* risk     = anomaly + NN;               // N
  float* resource = risk + NN;                  // N*5
  float* glog     = resource + (size_t)NN * 5;  // G*4

  static int smem_set = 0;
  if (!smem_set) {
    cudaFuncSetAttribute((const void*)k_gemm_mma,
                         cudaFuncAttributeMaxDynamicSharedMemorySize, SMEM_DYN);
    smem_set = 1;
  }

  dim3 gg(2, (NN + 127) / 128);
  int agg_grid = (NN * 32 + 255) / 256;

  k_init<<<(NN + 255) / 256, 256>>>();
  k_degree<<<(NE + 255) / 256, 256>>>(ei);
  k_xsplit<<<(NN * 128 + 255) / 256, 256>>>(x);
  k_bsplit<<<(256 * 128 + 255) / 256, 256>>>(W1, 128, 0);
  k_bsplit<<<(256 * 64 + 255) / 256, 256>>>(W2, 64, 1);
  k_bsplit<<<(256 * 64 + 255) / 256, 256>>>(W3, 64, 2);
  k_gemm_mma<<<gg, 256, SMEM_DYN>>>(128, as1, ad1, 0);
  k_scan<<<1, 1024>>>();
  k_scatter<<<(NE2 + 255) / 256, 256>>>(ei);
  k_agg<<<agg_grid, 256>>>(b1, nullptr, 0);

  // layer 2 (K=64)
  k_gemm_mma<<<gg, 256, SMEM_DYN>>>(64, as2, ad2, 1);
  k_agg<<<agg_grid, 256>>>(b2, nullptr, 0);
  // layer 3 (K=64)
  k_gemm_mma<<<gg, 256, SMEM_DYN>>>(64, as3, ad3, 2);
  k_agg<<<agg_grid, 256>>>(b3, emb, 1);

  // heads
  k_node_mlp<<<agg_grid, 256>>>(emb, batch, aw1, ab1, aw2, ab2,
                                rw1, rb1, rw2, rb2, cw1, cb1, cw2, cb2,
                                anomaly, risk, resource);
  k_graph_head<<<NG, 32>>>(gw1, gb1, gw2, gb2, glog);
}

// round 13
// speedup vs baseline: 1.0132x; 1.0132x over previous
#include <cuda_runtime.h>
#include <cuda_bf16.h>
#include <cuda_fp16.h>
#include <cstdint>

#define NN 50000
#define NE 800000
#define NE2 850000   /* NE + NN self loops */
#define NG 64

// ---------------- device scratch (no allocations allowed) ----------------
__device__ __align__(16) __half g_h16[NN * 256]; // per-layer h = x@W  [N, H*C] fp16
__device__ __align__(16) float g_x[NN * 64];    // layer activation buffer [N, 64]
__device__ __align__(16) float g_als[NN * 4];
__device__ __align__(16) float g_ald[NN * 4];
__device__ __align__(16) float g_alpha[NE2 * 4]; // overflow fallback only
__device__ __align__(16) __nv_bfloat16 g_bthi[256 * 128]; // W^T split hi [n][k]
__device__ __align__(16) __nv_bfloat16 g_btlo[256 * 128]; // W^T split lo [n][k]
__device__ int   g_deg[NN];
__device__ int   g_offs[NN + 1];
__device__ int   g_cursor[NN];
__device__ int   g_ssrc[NE2];
__device__ float g_psum[NG * 64];
__device__ float g_pcnt[NG];

// ---------------- CSR build ----------------
__global__ void k_init() {
  int i = blockIdx.x * blockDim.x + threadIdx.x;
  if (i < NN) g_deg[i] = 1;              // self-loop pre-counted
  if (i < NG * 64) g_psum[i] = 0.f;
  if (i < NG) g_pcnt[i] = 0.f;
}

__global__ void k_degree(const int* __restrict__ ei) {
  int e = blockIdx.x * blockDim.x + threadIdx.x;
  if (e < NE) atomicAdd(&g_deg[ei[NE + e]], 1);
}

__global__ void k_scan() {
  __shared__ int sums[1024];
  const int CH = (NN + 1023) / 1024;   // 49
  int t = threadIdx.x;
  int base = t * CH;
  int s = 0;
  for (int i = 0; i < CH; i++) { int idx = base + i; if (idx < NN) s += g_deg[idx]; }
  sums[t] = s;
  __syncthreads();
  for (int off = 1; off < 1024; off <<= 1) {
    int v = (t >= off) ? sums[t - off] : 0;
    __syncthreads();
    sums[t] += v;
    __syncthreads();
  }
  int run = (t == 0) ? 0 : sums[t - 1];
  for (int i = 0; i < CH; i++) {
    int idx = base + i;
    if (idx < NN) { g_offs[idx] = run; g_cursor[idx] = run; run += g_deg[idx]; }
  }
  if (t == 0) g_offs[NN] = sums[1023];
}

__global__ void k_scatter(const int* __restrict__ ei) {
  int e = blockIdx.x * blockDim.x + threadIdx.x;
  if (e >= NE2) return;
  int s, d;
  if (e < NE) { s = ei[e]; d = ei[NE + e]; }
  else        { s = e - NE; d = s; }
  int pos = atomicAdd(&g_cursor[d], 1);
  g_ssrc[pos] = s;
}

// ---------------- W split+transpose: W[K][256] fp32 -> g_bthi/lo [256][K] bf16 ----
__global__ void k_bsplit(const float* __restrict__ W, int K) {
  int idx = blockIdx.x * blockDim.x + threadIdx.x;
  if (idx >= 256 * K) return;
  int n = idx / K, k = idx - n * K;
  float v = W[k * 256 + n];
  __nv_bfloat16 hi = __float2bfloat16(v);
  __nv_bfloat16 lo = __float2bfloat16(v - __bfloat162float(hi));
  g_bthi[idx] = hi;
  g_btlo[idx] = lo;
}

// ---------------- tensor-core GEMM + fused attention logits ----------------
__device__ __forceinline__ void mma_bf16(float* c, const uint32_t* a, uint32_t b0, uint32_t b1) {
  asm volatile(
      "mma.sync.aligned.m16n8k16.row.col.f32.bf16.bf16.f32 "
      "{%0,%1,%2,%3}, {%4,%5,%6,%7}, {%8,%9}, {%0,%1,%2,%3};\n"
      : "+f"(c[0]), "+f"(c[1]), "+f"(c[2]), "+f"(c[3])
      : "r"(a[0]), "r"(a[1]), "r"(a[2]), "r"(a[3]), "r"(b0), "r"(b1));
}

__device__ __forceinline__ void ldsm4(uint32_t& r0, uint32_t& r1, uint32_t& r2, uint32_t& r3,
                                      uint32_t addr) {
  asm volatile("ldmatrix.sync.aligned.m8n8.x4.shared.b16 {%0,%1,%2,%3}, [%4];"
               : "=r"(r0), "=r"(r1), "=r"(r2), "=r"(r3) : "r"(addr));
}

#define SSTR 40

__global__ void __launch_bounds__(256, 2)
k_gemm_mma(const float* __restrict__ Ain, int K,
           const float* __restrict__ as_, const float* __restrict__ ad_) {
  const float* A = Ain ? Ain : g_x;
  __shared__ __nv_bfloat16 sAhi[128 * SSTR];
  __shared__ __nv_bfloat16 sAlo[128 * SSTR];
  __shared__ __nv_bfloat16 sBhi[128 * SSTR];
  __shared__ __nv_bfloat16 sBlo[128 * SSTR];

  const int bm = blockIdx.y * 128;
  const int bn = blockIdx.x * 128;
  const int tid = threadIdx.x;
  const int warp = tid >> 5, lane = tid & 31;
  const int wm = warp >> 1, wn = warp & 1;     // 4x2 warp grid
  const int gid = lane >> 2, tig = lane & 3;

  // ldmatrix lane-address components
  const int lt = lane >> 3, lr = lane & 7;
  const int a_row = (lt & 1) * 8 + lr;
  const int a_col = (lt >> 1) * 8;
  const int b_row = (lt >> 1) * 8 + lr;
  const int b_col = (lt & 1) * 8;

  const uint32_t uAhi = (uint32_t)__cvta_generic_to_shared(sAhi);
  const uint32_t uAlo = (uint32_t)__cvta_generic_to_shared(sAlo);
  const uint32_t uBhi = (uint32_t)__cvta_generic_to_shared(sBhi);
  const uint32_t uBlo = (uint32_t)__cvta_generic_to_shared(sBlo);

  float acc[2][8][4];
#pragma unroll
  for (int i = 0; i < 2; i++)
#pragma unroll
    for (int j = 0; j < 8; j++)
#pragma unroll
      for (int q = 0; q < 4; q++) acc[i][j][q] = 0.f;

  for (int k0 = 0; k0 < K; k0 += 32) {
    // --- stage A chunk [128][32] fp32 -> split bf16 hi/lo
#pragma unroll
    for (int it = 0; it < 4; it++) {
      int q = tid + 256 * it;
      int r = q >> 3, c = (q & 7) * 4;
      int gr = bm + r;
      float4 v = make_float4(0.f, 0.f, 0.f, 0.f);
      if (gr < NN) v = *(const float4*)(A + (size_t)gr * K + k0 + c);
      __nv_bfloat16 h0 = __float2bfloat16(v.x), h1 = __float2bfloat16(v.y);
      __nv_bfloat16 h2 = __float2bfloat16(v.z), h3 = __float2bfloat16(v.w);
      __nv_bfloat16 l0 = __float2bfloat16(v.x - __bfloat162float(h0));
      __nv_bfloat16 l1 = __float2bfloat16(v.y - __bfloat162float(h1));
      __nv_bfloat16 l2 = __float2bfloat16(v.z - __bfloat162float(h2));
      __nv_bfloat16 l3 = __float2bfloat16(v.w - __bfloat162float(h3));
      __nv_bfloat162* dh = (__nv_bfloat162*)&sAhi[r * SSTR + c];
      __nv_bfloat162* dl = (__nv_bfloat162*)&sAlo[r * SSTR + c];
      dh[0] = __halves2bfloat162(h0, h1);
      dh[1] = __halves2bfloat162(h2, h3);
      dl[0] = __halves2bfloat162(l0, l1);
      dl[1] = __halves2bfloat162(l2, l3);
    }
    // --- stage B chunk: g_bthi/lo [256][K] -> sB [n(128)][k(32)]
#pragma unroll
    for (int it = 0; it < 2; it++) {
      int q = tid + 256 * it;
      int nl = q >> 2, kq = (q & 3) * 8;
      const uint4* srch = (const uint4*)&g_bthi[(bn + nl) * K + k0 + kq];
      const uint4* srcl = (const uint4*)&g_btlo[(bn + nl) * K + k0 + kq];
      *(uint4*)&sBhi[nl * SSTR + kq] = *srch;
      *(uint4*)&sBlo[nl * SSTR + kq] = *srcl;
    }
    __syncthreads();

#pragma unroll
    for (int ks = 0; ks < 2; ks++) {
      const int kb = ks * 16;
      uint32_t ahi[2][4], alo[2][4];
#pragma unroll
      for (int i = 0; i < 2; i++) {
        uint32_t off = (uint32_t)(((wm * 32 + i * 16 + a_row) * SSTR + kb + a_col) * 2);
        ldsm4(ahi[i][0], ahi[i][1], ahi[i][2], ahi[i][3], uAhi + off);
        ldsm4(alo[i][0], alo[i][1], alo[i][2], alo[i][3], uAlo + off);
      }
#pragma unroll
      for (int jj = 0; jj < 4; jj++) {
        uint32_t off = (uint32_t)(((wn * 64 + jj * 16 + b_row) * SSTR + kb + b_col) * 2);
        uint32_t bh0, bh1, bh2, bh3, bl0, bl1, bl2, bl3;
        ldsm4(bh0, bh1, bh2, bh3, uBhi + off);
        ldsm4(bl0, bl1, bl2, bl3, uBlo + off);
#pragma unroll
        for (int i = 0; i < 2; i++) {
          mma_bf16(acc[i][jj * 2],     ahi[i], bh0, bh1);
          mma_bf16(acc[i][jj * 2],     ahi[i], bl0, bl1);
          mma_bf16(acc[i][jj * 2],     alo[i], bh0, bh1);
          mma_bf16(acc[i][jj * 2 + 1], ahi[i], bh2, bh3);
          mma_bf16(acc[i][jj * 2 + 1], ahi[i], bl2, bl3);
          mma_bf16(acc[i][jj * 2 + 1], alo[i], bh2, bh3);
        }
      }
    }
    __syncthreads();
  }

  // --- epilogue 1: write fp16 h
#pragma unroll
  for (int i = 0; i < 2; i++) {
#pragma unroll
    for (int j = 0; j < 8; j++) {
      int row = bm + wm * 32 + i * 16 + gid;
      int col = bn + wn * 64 + j * 8 + 2 * tig;
      __half2 p01 = __floats2half2_rn(acc[i][j][0], acc[i][j][1]);
      __half2 p23 = __floats2half2_rn(acc[i][j][2], acc[i][j][3]);
      if (row < NN)
        *(__half2*)(g_h16 + (size_t)row * 256 + col) = p01;
      if (row + 8 < NN)
        *(__half2*)(g_h16 + (size_t)(row + 8) * 256 + col) = p23;
    }
  }

  // --- epilogue 2: fused attention logits for head = 2*bn + wn
  {
    const int head = blockIdx.x * 2 + wn;
    float wa[16], wd[16];
#pragma unroll
    for (int j = 0; j < 8; j++) {
      int c = j * 8 + 2 * tig;
      wa[j * 2 + 0] = as_[head * 64 + c];
      wa[j * 2 + 1] = as_[head * 64 + c + 1];
      wd[j * 2 + 0] = ad_[head * 64 + c];
      wd[j * 2 + 1] = ad_[head * 64 + c + 1];
    }
#pragma unroll
    for (int i = 0; i < 2; i++) {
      float s0 = 0.f, s1 = 0.f, d0 = 0.f, d1 = 0.f;
#pragma unroll
      for (int j = 0; j < 8; j++) {
        s0 = fmaf(acc[i][j][0], wa[j * 2], fmaf(acc[i][j][1], wa[j * 2 + 1], s0));
        s1 = fmaf(acc[i][j][2], wa[j * 2], fmaf(acc[i][j][3], wa[j * 2 + 1], s1));
        d0 = fmaf(acc[i][j][0], wd[j * 2], fmaf(acc[i][j][1], wd[j * 2 + 1], d0));
        d1 = fmaf(acc[i][j][2], wd[j * 2], fmaf(acc[i][j][3], wd[j * 2 + 1], d1));
      }
#pragma unroll
      for (int o = 1; o <= 2; o <<= 1) {
        s0 += __shfl_xor_sync(0xffffffffu, s0, o);
        s1 += __shfl_xor_sync(0xffffffffu, s1, o);
        d0 += __shfl_xor_sync(0xffffffffu, d0, o);
        d1 += __shfl_xor_sync(0xffffffffu, d1, o);
      }
      if (tig == 0) {
        int row = bm + wm * 32 + i * 16 + gid;
        if (row < NN)     { g_als[row * 4 + head] = s0; g_ald[row * 4 + head] = d0; }
        if (row + 8 < NN) { g_als[(row + 8) * 4 + head] = s1; g_ald[(row + 8) * 4 + head] = d1; }
      }
    }
  }
}

// ---------------- softmax + aggregation: one warp per dst node ----------------
// Max-shift skipped: logits are O(1) by construction -> exp cannot overflow.
// Per-edge alpha cached in shared memory (gmem fallback for deg > 64).
// Phase B: HALF-WARP per edge -> 2 edges in flight, half the serial trip count.
__device__ __forceinline__ float leaky(float v) { return v >= 0.f ? v : 0.2f * v; }

#define ACAP 64

__global__ void __launch_bounds__(256)
k_agg(const float* __restrict__ bias, float* __restrict__ outp, int do_relu) {
  __shared__ float4 s_alpha[8][ACAP];
  int warp = (blockIdx.x * blockDim.x + threadIdx.x) >> 5;
  int wip = threadIdx.x >> 5;
  int lane = threadIdx.x & 31;
  if (warp >= NN) return;
  float* op = outp ? outp : g_x;
  const int n = warp;
  const int beg = g_offs[n], end = g_offs[n + 1];

  const float4 ald = *(const float4*)&g_ald[n * 4];

  float d0 = 0.f, d1 = 0.f, d2 = 0.f, d3 = 0.f;
  for (int e = beg + lane; e < end; e += 32) {
    int s = g_ssrc[e];
    float4 als = *(const float4*)&g_als[s * 4];
    float p0 = __expf(leaky(als.x + ald.x));
    float p1 = __expf(leaky(als.y + ald.y));
    float p2 = __expf(leaky(als.z + ald.z));
    float p3 = __expf(leaky(als.w + ald.w));
    d0 += p0; d1 += p1; d2 += p2; d3 += p3;
    int idx = e - beg;
    float4 pv = make_float4(p0, p1, p2, p3);
    if (idx < ACAP) s_alpha[wip][idx] = pv;
    else            *(float4*)&g_alpha[(size_t)e * 4] = pv;
  }
#pragma unroll
  for (int o = 16; o; o >>= 1) {
    d0 += __shfl_xor_sync(0xffffffffu, d0, o);
    d1 += __shfl_xor_sync(0xffffffffu, d1, o);
    d2 += __shfl_xor_sync(0xffffffffu, d2, o);
    d3 += __shfl_xor_sync(0xffffffffu, d3, o);
  }
  __syncwarp();

  // half-warp layout: hw = lane>>4 picks the edge stream; l = lane&15 picks feats.
  // load0 -> feats [8l, 8l+8)        head hA = l>>3
  // load1 -> feats [128+8l, ..)      head hB = 2 + (l>>3)
  const int hw = lane >> 4;
  const int l = lane & 15;
  const bool hiHead = (l & 8) != 0;
  const float rA = 1.0f / (hiHead ? d1 : d0);
  const float rB = 1.0f / (hiHead ? d3 : d2);

  float accA[8], accB[8];
#pragma unroll
  for (int i = 0; i < 8; i++) { accA[i] = 0.f; accB[i] = 0.f; }

  const int deg = end - beg;
  int idx = hw;
  for (; idx + 2 < deg; idx += 4) {   // unroll 2 per half-warp (stride 2 each)
    int sA_ = g_ssrc[beg + idx];
    int sB_ = g_ssrc[beg + idx + 2];
    float4 pA = (idx < ACAP) ? s_alpha[wip][idx] : *(const float4*)&g_alpha[(size_t)(beg + idx) * 4];
    float4 pB = (idx + 2 < ACAP) ? s_alpha[wip][idx + 2] : *(const float4*)&g_alpha[(size_t)(beg + idx + 2) * 4];
    const uint4* hpA = (const uint4*)(g_h16 + (size_t)sA_ * 256);
    const uint4* hpB = (const uint4*)(g_h16 + (size_t)sB_ * 256);
    uint4 rA0 = __ldg(hpA + l);
    uint4 rA1 = __ldg(hpA + 16 + l);
    uint4 rB0 = __ldg(hpB + l);
    uint4 rB1 = __ldg(hpB + 16 + l);
    float aA0 = (hiHead ? pA.y : pA.x) * rA;
    float aA1 = (hiHead ? pA.w : pA.z) * rB;
    float aB0 = (hiHead ? pB.y : pB.x) * rA;
    float aB1 = (hiHead ? pB.w : pB.z) * rB;
    const uint32_t* wA0 = (const uint32_t*)&rA0;
    const uint32_t* wA1 = (const uint32_t*)&rA1;
    const uint32_t* wB0 = (const uint32_t*)&rB0;
    const uint32_t* wB1 = (const uint32_t*)&rB1;
#pragma unroll
    for (int q = 0; q < 4; q++) {
      float2 f;
      f = __half22float2(*(const __half2*)&wA0[q]);
      accA[2 * q]     = fmaf(f.x, aA0, accA[2 * q]);
      accA[2 * q + 1] = fmaf(f.y, aA0, accA[2 * q + 1]);
      f = __half22float2(*(const __half2*)&wA1[q]);
      accB[2 * q]     = fmaf(f.x, aA1, accB[2 * q]);
      accB[2 * q + 1] = fmaf(f.y, aA1, accB[2 * q + 1]);
      f = __half22float2(*(const __half2*)&wB0[q]);
      accA[2 * q]     = fmaf(f.x, aB0, accA[2 * q]);
      accA[2 * q + 1] = fmaf(f.y, aB0, accA[2 * q + 1]);
      f = __half22float2(*(const __half2*)&wB1[q]);
      accB[2 * q]     = fmaf(f.x, aB1, accB[2 * q]);
      accB[2 * q + 1] = fmaf(f.y, aB1, accB[2 * q + 1]);
    }
  }
  for (; idx < deg; idx += 2) {
    int s = g_ssrc[beg + idx];
    float4 p = (idx < ACAP) ? s_alpha[wip][idx] : *(const float4*)&g_alpha[(size_t)(beg + idx) * 4];
    const uint4* hp = (const uint4*)(g_h16 + (size_t)s * 256);
    uint4 r0 = __ldg(hp + l);
    uint4 r1 = __ldg(hp + 16 + l);
    float a0 = (hiHead ? p.y : p.x) * rA;
    float a1 = (hiHead ? p.w : p.z) * rB;
    const uint32_t* w0 = (const uint32_t*)&r0;
    const uint32_t* w1 = (const uint32_t*)&r1;
#pragma unroll
    for (int q = 0; q < 4; q++) {
      float2 f;
      f = __half22float2(*(const __half2*)&w0[q]);
      accA[2 * q]     = fmaf(f.x, a0, accA[2 * q]);
      accA[2 * q + 1] = fmaf(f.y, a0, accA[2 * q + 1]);
      f = __half22float2(*(const __half2*)&w1[q]);
      accB[2 * q]     = fmaf(f.x, a1, accB[2 * q]);
      accB[2 * q + 1] = fmaf(f.y, a1, accB[2 * q + 1]);
    }
  }

  // combine: heads {hA, hA+2} summed; xor16 merges edge halves; xor8 merges head pairs.
  float t[8];
#pragma unroll
  for (int i = 0; i < 8; i++) t[i] = accA[i] + accB[i];
#pragma unroll
  for (int i = 0; i < 8; i++) {
    t[i] += __shfl_xor_sync(0xffffffffu, t[i], 16);
    t[i] += __shfl_xor_sync(0xffffffffu, t[i], 8);
  }
  if (lane < 8) {
    // lane covers output channels [8*lane, 8*lane+8)
    const float4 b0 = *(const float4*)(bias + lane * 8);
    const float4 b1 = *(const float4*)(bias + lane * 8 + 4);
    float o0 = t[0] * 0.25f + b0.x;
    float o1 = t[1] * 0.25f + b0.y;
    float o2 = t[2] * 0.25f + b0.z;
    float o3 = t[3] * 0.25f + b0.w;
    float o4 = t[4] * 0.25f + b1.x;
    float o5 = t[5] * 0.25f + b1.y;
    float o6 = t[6] * 0.25f + b1.z;
    float o7 = t[7] * 0.25f + b1.w;
    if (do_relu) {
      o0 = fmaxf(o0, 0.f); o1 = fmaxf(o1, 0.f); o2 = fmaxf(o2, 0.f); o3 = fmaxf(o3, 0.f);
      o4 = fmaxf(o4, 0.f); o5 = fmaxf(o5, 0.f); o6 = fmaxf(o6, 0.f); o7 = fmaxf(o7, 0.f);
    }
    float* dst = op + (size_t)n * 64 + lane * 8;
    *(float4*)dst = make_float4(o0, o1, o2, o3);
    *(float4*)(dst + 4) = make_float4(o4, o5, o6, o7);
  }
}

// ---------------- node MLP heads + pooling ----------------
__device__ __forceinline__ float sigmoidf_(float x) { return 1.0f / (1.0f + __expf(-x)); }

__global__ void k_node_mlp(const float* __restrict__ emb, const int* __restrict__ batch,
                           const float* __restrict__ aw1, const float* __restrict__ ab1,
                           const float* __restrict__ aw2, const float* __restrict__ ab2,
                           const float* __restrict__ rw1, const float* __restrict__ rb1,
                           const float* __restrict__ rw2, const float* __restrict__ rb2,
                           const float* __restrict__ cw1, const float* __restrict__ cb1,
                           const float* __restrict__ cw2, const float* __restrict__ cb2,
                           float* __restrict__ anomaly, float* __restrict__ risk,
                           float* __restrict__ resource) {
  int warp = (blockIdx.x * blockDim.x + threadIdx.x) >> 5;
  int lane = threadIdx.x & 31;
  if (warp >= NN) return;
  int n = warp;
  float e0 = emb[(size_t)n * 64 + lane];
  float e1 = emb[(size_t)n * 64 + 32 + lane];

  float ha = ab1[lane], hr = rb1[lane], hc = cb1[lane];
#pragma unroll
  for (int k = 0; k < 32; k++) {
    float ek = __shfl_sync(0xffffffffu, e0, k);
    ha = fmaf(ek, aw1[k * 32 + lane], ha);
    hr = fmaf(ek, rw1[k * 32 + lane], hr);
    hc = fmaf(ek, cw1[k * 32 + lane], hc);
  }
#pragma unroll
  for (int k = 0; k < 32; k++) {
    float ek = __shfl_sync(0xffffffffu, e1, k);
    ha = fmaf(ek, aw1[(k + 32) * 32 + lane], ha);
    hr = fmaf(ek, rw1[(k + 32) * 32 + lane], hr);
    hc = fmaf(ek, cw1[(k + 32) * 32 + lane], hc);
  }
  ha = fmaxf(ha, 0.f); hr = fmaxf(hr, 0.f); hc = fmaxf(hc, 0.f);

  float va = ha * aw2[lane];
  float vr = hr * rw2[lane];
#pragma unroll
  for (int o = 16; o; o >>= 1) {
    va += __shfl_xor_sync(0xffffffffu, va, o);
    vr += __shfl_xor_sync(0xffffffffu, vr, o);
  }
  if (lane == 0) {
    anomaly[n] = sigmoidf_(va + ab2[0]);
    risk[n]    = sigmoidf_(vr + rb2[0]);
  }
#pragma unroll
  for (int o5 = 0; o5 < 5; o5++) {
    float vc = hc * cw2[lane * 5 + o5];
#pragma unroll
    for (int o = 16; o; o >>= 1) vc += __shfl_xor_sync(0xffffffffu, vc, o);
    if (lane == 0) resource[(size_t)n * 5 + o5] = vc + cb2[o5];
  }

  int g = batch[n];
  atomicAdd(&g_psum[g * 64 + lane], e0);
  atomicAdd(&g_psum[g * 64 + 32 + lane], e1);
  if (lane == 0) atomicAdd(&g_pcnt[g], 1.0f);
}

__global__ void k_graph_head(const float* __restrict__ gw1, const float* __restrict__ gb1,
                             const float* __restrict__ gw2, const float* __restrict__ gb2,
                             float* __restrict__ glog) {
  int g = blockIdx.x;
  int lane = threadIdx.x;
  float rc = 1.0f / fmaxf(g_pcnt[g], 1.0f);
  float hid = gb1[lane];
#pragma unroll
  for (int c = 0; c < 64; c++)
    hid = fmaf(g_psum[g * 64 + c] * rc, gw1[c * 32 + lane], hid);
  hid = fmaxf(hid, 0.f);
#pragma unroll
  for (int o4 = 0; o4 < 4; o4++) {
    float v = hid * gw2[lane * 4 + o4];
#pragma unroll
    for (int o = 16; o; o >>= 1) v += __shfl_xor_sync(0xffffffffu, v, o);
    if (lane == 0) glog[g * 4 + o4] = v + gb2[o4];
  }
}

// ---------------- launch ----------------
extern "C" void kernel_launch(void* const* d_in, const int* in_sizes, int n_in,
                              void* d_out, int out_size) {
  const float* x    = (const float*)d_in[0];
  const int*   ei   = (const int*)d_in[1];
  const int*   batch= (const int*)d_in[2];
  const float* W1   = (const float*)d_in[3];
  const float* as1  = (const float*)d_in[4];
  const float* ad1  = (const float*)d_in[5];
  const float* b1   = (const float*)d_in[6];
  const float* W2   = (const float*)d_in[7];
  const float* as2  = (const float*)d_in[8];
  const float* ad2  = (const float*)d_in[9];
  const float* b2   = (const float*)d_in[10];
  const float* W3   = (const float*)d_in[11];
  const float* as3  = (const float*)d_in[12];
  const float* ad3  = (const float*)d_in[13];
  const float* b3   = (const float*)d_in[14];
  const float* aw1  = (const float*)d_in[15];
  const float* ab1  = (const float*)d_in[16];
  const float* aw2  = (const float*)d_in[17];
  const float* ab2  = (const float*)d_in[18];
  const float* rw1  = (const float*)d_in[19];
  const float* rb1  = (const float*)d_in[20];
  const float* rw2  = (const float*)d_in[21];
  const float* rb2  = (const float*)d_in[22];
  const float* cw1  = (const float*)d_in[23];
  const float* cb1  = (const float*)d_in[24];
  const float* cw2  = (const float*)d_in[25];
  const float* cb2  = (const float*)d_in[26];
  const float* gw1  = (const float*)d_in[27];
  const float* gb1  = (const float*)d_in[28];
  const float* gw2  = (const float*)d_in[29];
  const float* gb2  = (const float*)d_in[30];

  float* out      = (float*)d_out;
  float* emb      = out;                        // N*64
  float* anomaly  = out + (size_t)NN * 64;      // N
  float* risk     = anomaly + NN;               // N
  float* resource = risk + NN;                  // N*5
  float* glog     = resource + (size_t)NN * 5;  // G*4

  dim3 gg(2, (NN + 127) / 128);
  int agg_grid = (NN * 32 + 255) / 256;

  k_init<<<(NN + 255) / 256, 256>>>();
  k_degree<<<(NE + 255) / 256, 256>>>(ei);
  k_bsplit<<<(256 * 128 + 255) / 256, 256>>>(W1, 128);
  k_gemm_mma<<<gg, 256>>>(x, 128, as1, ad1);
  k_scan<<<1, 1024>>>();
  k_scatter<<<(NE2 + 255) / 256, 256>>>(ei);
  k_agg<<<agg_grid, 256>>>(b1, nullptr, 1);

  // layer 2 (K=64)
  k_bsplit<<<(256 * 64 + 255) / 256, 256>>>(W2, 64);
  k_gemm_mma<<<gg, 256>>>(nullptr, 64, as2, ad2);
  k_agg<<<agg_grid, 256>>>(b2, nullptr, 1);
  // layer 3 (K=64)
  k_bsplit<<<(256 * 64 + 255) / 256, 256>>>(W3, 64);
  k_gemm_mma<<<gg, 256>>>(nullptr, 64, as3, ad3);
  k_agg<<<agg_grid, 256>>>(b3, emb, 0);

  // heads
  k_node_mlp<<<agg_grid, 256>>>(emb, batch, aw1, ab1, aw2, ab2,
                                rw1, rb1, rw2, rb2, cw1, cb1, cw2, cb2,
                                anomaly, risk, resource);
  k_graph_head<<<NG, 32>>>(gw1, gb1, gw2, gb2, glog);
}

// round 14
// speedup vs baseline: 1.1004x; 1.0860x over previous
#include <cuda_runtime.h>
#include <cuda_bf16.h>
#include <cuda_fp16.h>
#include <cstdint>

#define NN 50000
#define NE 800000
#define NE2 850000   /* NE + NN self loops */
#define NG 64

// ---------------- device scratch (no allocations allowed) ----------------
__device__ __align__(16) __half g_h16[NN * 256]; // per-layer h = x@W  [N, H*C] fp16
__device__ __align__(16) float g_x[NN * 64];    // layer activation buffer [N, 64]
__device__ __align__(16) float g_als[NN * 4];
__device__ __align__(16) float g_ald[NN * 4];
__device__ __align__(16) float g_alpha[NE2 * 4]; // overflow fallback only
__device__ __align__(16) __nv_bfloat16 g_bthi[256 * 128]; // W^T split hi [n][k]
__device__ __align__(16) __nv_bfloat16 g_btlo[256 * 128]; // W^T split lo [n][k]
__device__ int   g_deg[NN];
__device__ int   g_offs[NN + 1];
__device__ int   g_cursor[NN];
__device__ int   g_ssrc[NE2];
__device__ float g_psum[NG * 64];
__device__ float g_pcnt[NG];

// ---------------- CSR build ----------------
__global__ void k_init() {
  int i = blockIdx.x * blockDim.x + threadIdx.x;
  if (i < NN) g_deg[i] = 1;              // self-loop pre-counted
  if (i < NG * 64) g_psum[i] = 0.f;
  if (i < NG) g_pcnt[i] = 0.f;
}

__global__ void k_degree(const int* __restrict__ ei) {
  int e = blockIdx.x * blockDim.x + threadIdx.x;
  if (e < NE) atomicAdd(&g_deg[ei[NE + e]], 1);
}

__global__ void k_scan() {
  __shared__ int sums[1024];
  const int CH = (NN + 1023) / 1024;   // 49
  int t = threadIdx.x;
  int base = t * CH;
  int s = 0;
  for (int i = 0; i < CH; i++) { int idx = base + i; if (idx < NN) s += g_deg[idx]; }
  sums[t] = s;
  __syncthreads();
  for (int off = 1; off < 1024; off <<= 1) {
    int v = (t >= off) ? sums[t - off] : 0;
    __syncthreads();
    sums[t] += v;
    __syncthreads();
  }
  int run = (t == 0) ? 0 : sums[t - 1];
  for (int i = 0; i < CH; i++) {
    int idx = base + i;
    if (idx < NN) { g_offs[idx] = run; g_cursor[idx] = run; run += g_deg[idx]; }
  }
  if (t == 0) g_offs[NN] = sums[1023];
}

__global__ void k_scatter(const int* __restrict__ ei) {
  int e = blockIdx.x * blockDim.x + threadIdx.x;
  if (e >= NE2) return;
  int s, d;
  if (e < NE) { s = ei[e]; d = ei[NE + e]; }
  else        { s = e - NE; d = s; }
  int pos = atomicAdd(&g_cursor[d], 1);
  g_ssrc[pos] = s;
}

// ---------------- W split+transpose: W[K][256] fp32 -> g_bthi/lo [256][K] bf16 ----
__global__ void k_bsplit(const float* __restrict__ W, int K) {
  int idx = blockIdx.x * blockDim.x + threadIdx.x;
  if (idx >= 256 * K) return;
  int n = idx / K, k = idx - n * K;
  float v = W[k * 256 + n];
  __nv_bfloat16 hi = __float2bfloat16(v);
  __nv_bfloat16 lo = __float2bfloat16(v - __bfloat162float(hi));
  g_bthi[idx] = hi;
  g_btlo[idx] = lo;
}

// ---------------- tensor-core GEMM + fused attention logits ----------------
__device__ __forceinline__ void mma_bf16(float* c, const uint32_t* a, uint32_t b0, uint32_t b1) {
  asm volatile(
      "mma.sync.aligned.m16n8k16.row.col.f32.bf16.bf16.f32 "
      "{%0,%1,%2,%3}, {%4,%5,%6,%7}, {%8,%9}, {%0,%1,%2,%3};\n"
      : "+f"(c[0]), "+f"(c[1]), "+f"(c[2]), "+f"(c[3])
      : "r"(a[0]), "r"(a[1]), "r"(a[2]), "r"(a[3]), "r"(b0), "r"(b1));
}

__device__ __forceinline__ void ldsm4(uint32_t& r0, uint32_t& r1, uint32_t& r2, uint32_t& r3,
                                      uint32_t addr) {
  asm volatile("ldmatrix.sync.aligned.m8n8.x4.shared.b16 {%0,%1,%2,%3}, [%4];"
               : "=r"(r0), "=r"(r1), "=r"(r2), "=r"(r3) : "r"(addr));
}

#define SSTR 40

__global__ void __launch_bounds__(256, 2)
k_gemm_mma(const float* __restrict__ Ain, int K,
           const float* __restrict__ as_, const float* __restrict__ ad_) {
  const float* A = Ain ? Ain : g_x;
  __shared__ __nv_bfloat16 sAhi[128 * SSTR];
  __shared__ __nv_bfloat16 sAlo[128 * SSTR];
  __shared__ __nv_bfloat16 sBhi[128 * SSTR];
  __shared__ __nv_bfloat16 sBlo[128 * SSTR];

  const int bm = blockIdx.y * 128;
  const int bn = blockIdx.x * 128;
  const int tid = threadIdx.x;
  const int warp = tid >> 5, lane = tid & 31;
  const int wm = warp >> 1, wn = warp & 1;     // 4x2 warp grid
  const int gid = lane >> 2, tig = lane & 3;

  // ldmatrix lane-address components
  const int lt = lane >> 3, lr = lane & 7;
  const int a_row = (lt & 1) * 8 + lr;
  const int a_col = (lt >> 1) * 8;
  const int b_row = (lt >> 1) * 8 + lr;
  const int b_col = (lt & 1) * 8;

  const uint32_t uAhi = (uint32_t)__cvta_generic_to_shared(sAhi);
  const uint32_t uAlo = (uint32_t)__cvta_generic_to_shared(sAlo);
  const uint32_t uBhi = (uint32_t)__cvta_generic_to_shared(sBhi);
  const uint32_t uBlo = (uint32_t)__cvta_generic_to_shared(sBlo);

  float acc[2][8][4];
#pragma unroll
  for (int i = 0; i < 2; i++)
#pragma unroll
    for (int j = 0; j < 8; j++)
#pragma unroll
      for (int q = 0; q < 4; q++) acc[i][j][q] = 0.f;

  for (int k0 = 0; k0 < K; k0 += 32) {
    // --- stage A chunk [128][32] fp32 -> split bf16 hi/lo
#pragma unroll
    for (int it = 0; it < 4; it++) {
      int q = tid + 256 * it;
      int r = q >> 3, c = (q & 7) * 4;
      int gr = bm + r;
      float4 v = make_float4(0.f, 0.f, 0.f, 0.f);
      if (gr < NN) v = *(const float4*)(A + (size_t)gr * K + k0 + c);
      __nv_bfloat16 h0 = __float2bfloat16(v.x), h1 = __float2bfloat16(v.y);
      __nv_bfloat16 h2 = __float2bfloat16(v.z), h3 = __float2bfloat16(v.w);
      __nv_bfloat16 l0 = __float2bfloat16(v.x - __bfloat162float(h0));
      __nv_bfloat16 l1 = __float2bfloat16(v.y - __bfloat162float(h1));
      __nv_bfloat16 l2 = __float2bfloat16(v.z - __bfloat162float(h2));
      __nv_bfloat16 l3 = __float2bfloat16(v.w - __bfloat162float(h3));
      __nv_bfloat162* dh = (__nv_bfloat162*)&sAhi[r * SSTR + c];
      __nv_bfloat162* dl = (__nv_bfloat162*)&sAlo[r * SSTR + c];
      dh[0] = __halves2bfloat162(h0, h1);
      dh[1] = __halves2bfloat162(h2, h3);
      dl[0] = __halves2bfloat162(l0, l1);
      dl[1] = __halves2bfloat162(l2, l3);
    }
    // --- stage B chunk: g_bthi/lo [256][K] -> sB [n(128)][k(32)]
#pragma unroll
    for (int it = 0; it < 2; it++) {
      int q = tid + 256 * it;
      int nl = q >> 2, kq = (q & 3) * 8;
      const uint4* srch = (const uint4*)&g_bthi[(bn + nl) * K + k0 + kq];
      const uint4* srcl = (const uint4*)&g_btlo[(bn + nl) * K + k0 + kq];
      *(uint4*)&sBhi[nl * SSTR + kq] = *srch;
      *(uint4*)&sBlo[nl * SSTR + kq] = *srcl;
    }
    __syncthreads();

#pragma unroll
    for (int ks = 0; ks < 2; ks++) {
      const int kb = ks * 16;
      uint32_t ahi[2][4], alo[2][4];
#pragma unroll
      for (int i = 0; i < 2; i++) {
        uint32_t off = (uint32_t)(((wm * 32 + i * 16 + a_row) * SSTR + kb + a_col) * 2);
        ldsm4(ahi[i][0], ahi[i][1], ahi[i][2], ahi[i][3], uAhi + off);
        ldsm4(alo[i][0], alo[i][1], alo[i][2], alo[i][3], uAlo + off);
      }
#pragma unroll
      for (int jj = 0; jj < 4; jj++) {
        uint32_t off = (uint32_t)(((wn * 64 + jj * 16 + b_row) * SSTR + kb + b_col) * 2);
        uint32_t bh0, bh1, bh2, bh3, bl0, bl1, bl2, bl3;
        ldsm4(bh0, bh1, bh2, bh3, uBhi + off);
        ldsm4(bl0, bl1, bl2, bl3, uBlo + off);
#pragma unroll
        for (int i = 0; i < 2; i++) {
          mma_bf16(acc[i][jj * 2],     ahi[i], bh0, bh1);
          mma_bf16(acc[i][jj * 2],     ahi[i], bl0, bl1);
          mma_bf16(acc[i][jj * 2],     alo[i], bh0, bh1);
          mma_bf16(acc[i][jj * 2 + 1], ahi[i], bh2, bh3);
          mma_bf16(acc[i][jj * 2 + 1], ahi[i], bl2, bl3);
          mma_bf16(acc[i][jj * 2 + 1], alo[i], bh2, bh3);
        }
      }
    }
    __syncthreads();
  }

  // --- epilogue 1: write fp16 h
#pragma unroll
  for (int i = 0; i < 2; i++) {
#pragma unroll
    for (int j = 0; j < 8; j++) {
      int row = bm + wm * 32 + i * 16 + gid;
      int col = bn + wn * 64 + j * 8 + 2 * tig;
      __half2 p01 = __floats2half2_rn(acc[i][j][0], acc[i][j][1]);
      __half2 p23 = __floats2half2_rn(acc[i][j][2], acc[i][j][3]);
      if (row < NN)
        *(__half2*)(g_h16 + (size_t)row * 256 + col) = p01;
      if (row + 8 < NN)
        *(__half2*)(g_h16 + (size_t)(row + 8) * 256 + col) = p23;
    }
  }

  // --- epilogue 2: fused attention logits for head = 2*bn + wn
  {
    const int head = blockIdx.x * 2 + wn;
    float wa[16], wd[16];
#pragma unroll
    for (int j = 0; j < 8; j++) {
      int c = j * 8 + 2 * tig;
      wa[j * 2 + 0] = as_[head * 64 + c];
      wa[j * 2 + 1] = as_[head * 64 + c + 1];
      wd[j * 2 + 0] = ad_[head * 64 + c];
      wd[j * 2 + 1] = ad_[head * 64 + c + 1];
    }
#pragma unroll
    for (int i = 0; i < 2; i++) {
      float s0 = 0.f, s1 = 0.f, d0 = 0.f, d1 = 0.f;
#pragma unroll
      for (int j = 0; j < 8; j++) {
        s0 = fmaf(acc[i][j][0], wa[j * 2], fmaf(acc[i][j][1], wa[j * 2 + 1], s0));
        s1 = fmaf(acc[i][j][2], wa[j * 2], fmaf(acc[i][j][3], wa[j * 2 + 1], s1));
        d0 = fmaf(acc[i][j][0], wd[j * 2], fmaf(acc[i][j][1], wd[j * 2 + 1], d0));
        d1 = fmaf(acc[i][j][2], wd[j * 2], fmaf(acc[i][j][3], wd[j * 2 + 1], d1));
      }
#pragma unroll
      for (int o = 1; o <= 2; o <<= 1) {
        s0 += __shfl_xor_sync(0xffffffffu, s0, o);
        s1 += __shfl_xor_sync(0xffffffffu, s1, o);
        d0 += __shfl_xor_sync(0xffffffffu, d0, o);
        d1 += __shfl_xor_sync(0xffffffffu, d1, o);
      }
      if (tig == 0) {
        int row = bm + wm * 32 + i * 16 + gid;
        if (row < NN)     { g_als[row * 4 + head] = s0; g_ald[row * 4 + head] = d0; }
        if (row + 8 < NN) { g_als[(row + 8) * 4 + head] = s1; g_ald[(row + 8) * 4 + head] = d1; }
      }
    }
  }
}

// ---------------- softmax + aggregation: one warp per dst node ----------------
// Max-shift skipped: logits are O(1) by construction -> exp cannot overflow.
// Per-edge alpha cached in shared memory (gmem fallback for deg > 64).
// Phase B accumulates groups of 4 edges in half2 (HFMA2, full-rate FMA pipe),
// flushing to fp32 once per group: conversion-pipe ops drop ~2.7x per edge.
__device__ __forceinline__ float leaky(float v) { return v >= 0.f ? v : 0.2f * v; }

#define ACAP 64

__global__ void __launch_bounds__(256)
k_agg(const float* __restrict__ bias, float* __restrict__ outp, int do_relu) {
  __shared__ float4 s_alpha[8][ACAP];
  int warp = (blockIdx.x * blockDim.x + threadIdx.x) >> 5;
  int wip = threadIdx.x >> 5;
  int lane = threadIdx.x & 31;
  if (warp >= NN) return;
  float* op = outp ? outp : g_x;
  const int n = warp;
  const int beg = g_offs[n], end = g_offs[n + 1];

  const float4 ald = *(const float4*)&g_ald[n * 4];

  float d0 = 0.f, d1 = 0.f, d2 = 0.f, d3 = 0.f;
  for (int e = beg + lane; e < end; e += 32) {
    int s = g_ssrc[e];
    float4 als = *(const float4*)&g_als[s * 4];
    float p0 = __expf(leaky(als.x + ald.x));
    float p1 = __expf(leaky(als.y + ald.y));
    float p2 = __expf(leaky(als.z + ald.z));
    float p3 = __expf(leaky(als.w + ald.w));
    d0 += p0; d1 += p1; d2 += p2; d3 += p3;
    int idx = e - beg;
    float4 pv = make_float4(p0, p1, p2, p3);
    if (idx < ACAP) s_alpha[wip][idx] = pv;
    else            *(float4*)&g_alpha[(size_t)e * 4] = pv;
  }
#pragma unroll
  for (int o = 16; o; o >>= 1) {
    d0 += __shfl_xor_sync(0xffffffffu, d0, o);
    d1 += __shfl_xor_sync(0xffffffffu, d1, o);
    d2 += __shfl_xor_sync(0xffffffffu, d2, o);
    d3 += __shfl_xor_sync(0xffffffffu, d3, o);
  }
  __syncwarp();

  const bool hs = (lane & 16) != 0;
  const float rA = 1.0f / (hs ? d1 : d0);
  const float rB = 1.0f / (hs ? d3 : d2);

  // phase B: warp-serial over edges (unroll 4); lanes cover 256 feats.
  float4 acc0 = make_float4(0.f, 0.f, 0.f, 0.f);
  float4 acc1 = make_float4(0.f, 0.f, 0.f, 0.f);
  const int deg = end - beg;
  int idx = 0;
  for (; idx + 3 < deg; idx += 4) {
    int s[4]; float4 p[4]; uint2 r0[4], r1[4];
#pragma unroll
    for (int j = 0; j < 4; j++) s[j] = g_ssrc[beg + idx + j];
#pragma unroll
    for (int j = 0; j < 4; j++)
      p[j] = (idx + j < ACAP) ? s_alpha[wip][idx + j]
                              : *(const float4*)&g_alpha[(size_t)(beg + idx + j) * 4];
#pragma unroll
    for (int j = 0; j < 4; j++) {
      const uint2* hp = (const uint2*)(g_h16 + (size_t)s[j] * 256);
      r0[j] = __ldg(hp + lane);
      r1[j] = __ldg(hp + 32 + lane);
    }
    // half2 accumulation over this 4-edge group (|partial| <= ~120 << fp16 max)
    __half2 hc0a = __float2half2_rn(0.f), hc0b = __float2half2_rn(0.f);
    __half2 hc1a = __float2half2_rn(0.f), hc1b = __float2half2_rn(0.f);
#pragma unroll
    for (int j = 0; j < 4; j++) {
      float a0 = (hs ? p[j].y : p[j].x) * rA;
      float a1 = (hs ? p[j].w : p[j].z) * rB;
      __half2 apk = __floats2half2_rn(a0, a1);   // 1 pack per edge
      __half2 ah0 = __low2half2(apk);            // (a0,a0) - ALU broadcast
      __half2 ah1 = __high2half2(apk);           // (a1,a1)
      hc0a = __hfma2(*(const __half2*)&r0[j].x, ah0, hc0a);
      hc0b = __hfma2(*(const __half2*)&r0[j].y, ah0, hc0b);
      hc1a = __hfma2(*(const __half2*)&r1[j].x, ah1, hc1a);
      hc1b = __hfma2(*(const __half2*)&r1[j].y, ah1, hc1b);
    }
    // flush group to fp32 (8 F2F per 4 edges instead of 32)
    float2 f;
    f = __half22float2(hc0a); acc0.x += f.x; acc0.y += f.y;
    f = __half22float2(hc0b); acc0.z += f.x; acc0.w += f.y;
    f = __half22float2(hc1a); acc1.x += f.x; acc1.y += f.y;
    f = __half22float2(hc1b); acc1.z += f.x; acc1.w += f.y;
  }
  for (; idx < deg; ++idx) {
    int s = g_ssrc[beg + idx];
    float4 p = (idx < ACAP) ? s_alpha[wip][idx] : *(const float4*)&g_alpha[(size_t)(beg + idx) * 4];
    float a0 = (hs ? p.y : p.x) * rA;
    float a1 = (hs ? p.w : p.z) * rB;
    const uint2* hp = (const uint2*)(g_h16 + (size_t)s * 256);
    uint2 r0 = __ldg(hp + lane);
    uint2 r1 = __ldg(hp + 32 + lane);
    float2 f;
    f = __half22float2(*(const __half2*)&r0.x); acc0.x = fmaf(f.x, a0, acc0.x); acc0.y = fmaf(f.y, a0, acc0.y);
    f = __half22float2(*(const __half2*)&r0.y); acc0.z = fmaf(f.x, a0, acc0.z); acc0.w = fmaf(f.y, a0, acc0.w);
    f = __half22float2(*(const __half2*)&r1.x); acc1.x = fmaf(f.x, a1, acc1.x); acc1.y = fmaf(f.y, a1, acc1.y);
    f = __half22float2(*(const __half2*)&r1.y); acc1.z = fmaf(f.x, a1, acc1.z); acc1.w = fmaf(f.y, a1, acc1.w);
  }

  float4 t;
  t.x = acc0.x + acc1.x; t.y = acc0.y + acc1.y;
  t.z = acc0.z + acc1.z; t.w = acc0.w + acc1.w;
  t.x += __shfl_xor_sync(0xffffffffu, t.x, 16);
  t.y += __shfl_xor_sync(0xffffffffu, t.y, 16);
  t.z += __shfl_xor_sync(0xffffffffu, t.z, 16);
  t.w += __shfl_xor_sync(0xffffffffu, t.w, 16);
  if (lane < 16) {
    const float4 b4 = *(const float4*)(bias + lane * 4);
    float4 o;
    o.x = t.x * 0.25f + b4.x;
    o.y = t.y * 0.25f + b4.y;
    o.z = t.z * 0.25f + b4.z;
    o.w = t.w * 0.25f + b4.w;
    if (do_relu) {
      o.x = fmaxf(o.x, 0.f); o.y = fmaxf(o.y, 0.f);
      o.z = fmaxf(o.z, 0.f); o.w = fmaxf(o.w, 0.f);
    }
    *(float4*)(op + (size_t)n * 64 + lane * 4) = o;
  }
}

// ---------------- node MLP heads + pooling ----------------
__device__ __forceinline__ float sigmoidf_(float x) { return 1.0f / (1.0f + __expf(-x)); }

__global__ void k_node_mlp(const float* __restrict__ emb, const int* __restrict__ batch,
                           const float* __restrict__ aw1, const float* __restrict__ ab1,
                           const float* __restrict__ aw2, const float* __restrict__ ab2,
                           const float* __restrict__ rw1, const float* __restrict__ rb1,
                           const float* __restrict__ rw2, const float* __restrict__ rb2,
                           const float* __restrict__ cw1, const float* __restrict__ cb1,
                           const float* __restrict__ cw2, const float* __restrict__ cb2,
                           float* __restrict__ anomaly, float* __restrict__ risk,
                           float* __restrict__ resource) {
  int warp = (blockIdx.x * blockDim.x + threadIdx.x) >> 5;
  int lane = threadIdx.x & 31;
  if (warp >= NN) return;
  int n = warp;
  float e0 = emb[(size_t)n * 64 + lane];
  float e1 = emb[(size_t)n * 64 + 32 + lane];

  float ha = ab1[lane], hr = rb1[lane], hc = cb1[lane];
#pragma unroll
  for (int k = 0; k < 32; k++) {
    float ek = __shfl_sync(0xffffffffu, e0, k);
    ha = fmaf(ek, aw1[k * 32 + lane], ha);
    hr = fmaf(ek, rw1[k * 32 + lane], hr);
    hc = fmaf(ek, cw1[k * 32 + lane], hc);
  }
#pragma unroll
  for (int k = 0; k < 32; k++) {
    float ek = __shfl_sync(0xffffffffu, e1, k);
    ha = fmaf(ek, aw1[(k + 32) * 32 + lane], ha);
    hr = fmaf(ek, rw1[(k + 32) * 32 + lane], hr);
    hc = fmaf(ek, cw1[(k + 32) * 32 + lane], hc);
  }
  ha = fmaxf(ha, 0.f); hr = fmaxf(hr, 0.f); hc = fmaxf(hc, 0.f);

  float va = ha * aw2[lane];
  float vr = hr * rw2[lane];
#pragma unroll
  for (int o = 16; o; o >>= 1) {
    va += __shfl_xor_sync(0xffffffffu, va, o);
    vr += __shfl_xor_sync(0xffffffffu, vr, o);
  }
  if (lane == 0) {
    anomaly[n] = sigmoidf_(va + ab2[0]);
    risk[n]    = sigmoidf_(vr + rb2[0]);
  }
#pragma unroll
  for (int o5 = 0; o5 < 5; o5++) {
    float vc = hc * cw2[lane * 5 + o5];
#pragma unroll
    for (int o = 16; o; o >>= 1) vc += __shfl_xor_sync(0xffffffffu, vc, o);
    if (lane == 0) resource[(size_t)n * 5 + o5] = vc + cb2[o5];
  }

  int g = batch[n];
  atomicAdd(&g_psum[g * 64 + lane], e0);
  atomicAdd(&g_psum[g * 64 + 32 + lane], e1);
  if (lane == 0) atomicAdd(&g_pcnt[g], 1.0f);
}

__global__ void k_graph_head(const float* __restrict__ gw1, const float* __restrict__ gb1,
                             const float* __restrict__ gw2, const float* __restrict__ gb2,
                             float* __restrict__ glog) {
  int g = blockIdx.x;
  int lane = threadIdx.x;
  float rc = 1.0f / fmaxf(g_pcnt[g], 1.0f);
  float hid = gb1[lane];
#pragma unroll
  for (int c = 0; c < 64; c++)
    hid = fmaf(g_psum[g * 64 + c] * rc, gw1[c * 32 + lane], hid);
  hid = fmaxf(hid, 0.f);
#pragma unroll
  for (int o4 = 0; o4 < 4; o4++) {
    float v = hid * gw2[lane * 4 + o4];
#pragma unroll
    for (int o = 16; o; o >>= 1) v += __shfl_xor_sync(0xffffffffu, v, o);
    if (lane == 0) glog[g * 4 + o4] = v + gb2[o4];
  }
}

// ---------------- launch ----------------
extern "C" void kernel_launch(void* const* d_in, const int* in_sizes, int n_in,
                              void* d_out, int out_size) {
  const float* x    = (const float*)d_in[0];
  const int*   ei   = (const int*)d_in[1];
  const int*   batch= (const int*)d_in[2];
  const float* W1   = (const float*)d_in[3];
  const float* as1  = (const float*)d_in[4];
  const float* ad1  = (const float*)d_in[5];
  const float* b1   = (const float*)d_in[6];
  const float* W2   = (const float*)d_in[7];
  const float* as2  = (const float*)d_in[8];
  const float* ad2  = (const float*)d_in[9];
  const float* b2   = (const float*)d_in[10];
  const float* W3   = (const float*)d_in[11];
  const float* as3  = (const float*)d_in[12];
  const float* ad3  = (const float*)d_in[13];
  const float* b3   = (const float*)d_in[14];
  const float* aw1  = (const float*)d_in[15];
  const float* ab1  = (const float*)d_in[16];
  const float* aw2  = (const float*)d_in[17];
  const float* ab2  = (const float*)d_in[18];
  const float* rw1  = (const float*)d_in[19];
  const float* rb1  = (const float*)d_in[20];
  const float* rw2  = (const float*)d_in[21];
  const float* rb2  = (const float*)d_in[22];
  const float* cw1  = (const float*)d_in[23];
  const float* cb1  = (const float*)d_in[24];
  const float* cw2  = (const float*)d_in[25];
  const float* cb2  = (const float*)d_in[26];
  const float* gw1  = (const float*)d_in[27];
  const float* gb1  = (const float*)d_in[28];
  const float* gw2  = (const float*)d_in[29];
  const float* gb2  = (const float*)d_in[30];

  float* out      = (float*)d_out;
  float* emb      = out;                        // N*64
  float* anomaly  = out + (size_t)NN * 64;      // N
  float* risk     = anomaly + NN;               // N
  float* resource = risk + NN;                  // N*5
  float* glog     = resource + (size_t)NN * 5;  // G*4

  dim3 gg(2, (NN + 127) / 128);
  int agg_grid = (NN * 32 + 255) / 256;

  k_init<<<(NN + 255) / 256, 256>>>();
  k_degree<<<(NE + 255) / 256, 256>>>(ei);
  k_bsplit<<<(256 * 128 + 255) / 256, 256>>>(W1, 128);
  k_gemm_mma<<<gg, 256>>>(x, 128, as1, ad1);
  k_scan<<<1, 1024>>>();
  k_scatter<<<(NE2 + 255) / 256, 256>>>(ei);
  k_agg<<<agg_grid, 256>>>(b1, nullptr, 1);

  // layer 2 (K=64)
  k_bsplit<<<(256 * 64 + 255) / 256, 256>>>(W2, 64);
  k_gemm_mma<<<gg, 256>>>(nullptr, 64, as2, ad2);
  k_agg<<<agg_grid, 256>>>(b2, nullptr, 1);
  // layer 3 (K=64)
  k_bsplit<<<(256 * 64 + 255) / 256, 256>>>(W3, 64);
  k_gemm_mma<<<gg, 256>>>(nullptr, 64, as3, ad3);
  k_agg<<<agg_grid, 256>>>(b3, emb, 0);

  // heads
  k_node_mlp<<<agg_grid, 256>>>(emb, batch, aw1, ab1, aw2, ab2,
                                rw1, rb1, rw2, rb2, cw1, cb1, cw2, cb2,
                                anomaly, risk, resource);
  k_graph_head<<<NG, 32>>>(gw1, gb1, gw2, gb2, glog);
}

// round 16
// speedup vs baseline: 1.3465x; 1.2237x over previous
#include <cuda_runtime.h>
#include <cuda_bf16.h>
#include <cuda_fp16.h>
#include <cstdint>

#define NN 50000
#define NE 800000
#define NE2 850000   /* NE + NN self loops */
#define NG 64
#define SCB 196      /* scan blocks: 196*256 >= NN */

// ---------------- device scratch (no allocations allowed) ----------------
__device__ __align__(16) __half g_h16[NN * 256]; // per-layer h = x@W  [N, H*C] fp16
__device__ __align__(16) float g_x[NN * 64];    // layer activation buffer [N, 64]
__device__ __align__(16) float g_als[NN * 4];
__device__ __align__(16) float g_ald[NN * 4];
__device__ __align__(16) float g_alpha[NE2 * 4]; // overflow fallback only
__device__ __align__(16) __nv_bfloat16 g_bthi[256 * 128]; // W^T split hi [n][k]
__device__ __align__(16) __nv_bfloat16 g_btlo[256 * 128]; // W^T split lo [n][k]
__device__ int   g_deg[NN];
__device__ int   g_offs[NN + 1];
__device__ int   g_cursor[NN];
__device__ int   g_ssrc[NE2];
__device__ int   g_bsum[256];
__device__ int   g_boff[256];
__device__ float g_psum[NG * 64];
__device__ float g_pcnt[NG];

// ---------------- CSR build ----------------
__global__ void k_init() {
  int i = blockIdx.x * blockDim.x + threadIdx.x;
  if (i < NN) g_deg[i] = 0;              // self-loop added analytically in scan
  if (i < NG * 64) g_psum[i] = 0.f;
  if (i < NG) g_pcnt[i] = 0.f;
}

__global__ void k_degree(const int* __restrict__ ei) {
  int t = blockIdx.x * blockDim.x + threadIdx.x;
  int e = t * 2;
  if (e + 1 < NE) {
    int2 d2 = *(const int2*)(ei + NE + e);
    atomicAdd(&g_deg[d2.x], 1);
    atomicAdd(&g_deg[d2.y], 1);
  } else if (e < NE) {
    atomicAdd(&g_deg[ei[NE + e]], 1);
  }
}

// scan phase 1: per-block sums of (deg+1)
__global__ void k_scan1() {
  __shared__ int ssum[8];
  int t = threadIdx.x;
  int i = blockIdx.x * 256 + t;
  int v = (i < NN) ? g_deg[i] + 1 : 0;
#pragma unroll
  for (int o = 16; o; o >>= 1) v += __shfl_xor_sync(0xffffffffu, v, o);
  if ((t & 31) == 0) ssum[t >> 5] = v;
  __syncthreads();
  if (t == 0) {
    int s = 0;
#pragma unroll
    for (int w = 0; w < 8; w++) s += ssum[w];
    g_bsum[blockIdx.x] = s;
  }
}

// scan phase 2: exclusive scan of block sums (single small block)
__global__ void k_scan2() {
  __shared__ int s[256];
  int t = threadIdx.x;
  int v = (t < SCB) ? g_bsum[t] : 0;
  s[t] = v;
  __syncthreads();
#pragma unroll
  for (int off = 1; off < 256; off <<= 1) {
    int u = (t >= off) ? s[t - off] : 0;
    __syncthreads();
    s[t] += u;
    __syncthreads();
  }
  if (t < SCB) g_boff[t] = s[t] - v;    // exclusive
  if (t == 0) g_offs[NN] = s[255];      // total = NE2
}

// scan phase 3: intra-block scan + write offsets/cursor
__global__ void k_scan3() {
  __shared__ int s[256];
  int t = threadIdx.x;
  int i = blockIdx.x * 256 + t;
  int v = (i < NN) ? g_deg[i] + 1 : 0;
  s[t] = v;
  __syncthreads();
#pragma unroll
  for (int off = 1; off < 256; off <<= 1) {
    int u = (t >= off) ? s[t - off] : 0;
    __syncthreads();
    s[t] += u;
    __syncthreads();
  }
  if (i < NN) {
    int off = g_boff[blockIdx.x] + s[t] - v;
    g_offs[i] = off;
    g_cursor[i] = off;
  }
}

__global__ void k_scatter(const int* __restrict__ ei) {
  int e = blockIdx.x * blockDim.x + threadIdx.x;
  if (e >= NE2) return;
  int s, d;
  if (e < NE) { s = ei[e]; d = ei[NE + e]; }
  else        { s = e - NE; d = s; }
  int pos = atomicAdd(&g_cursor[d], 1);
  g_ssrc[pos] = s;
}

// ---------------- W split+transpose: W[K][256] fp32 -> g_bthi/lo [256][K] bf16 ----
__global__ void k_bsplit(const float* __restrict__ W, int K) {
  int idx = blockIdx.x * blockDim.x + threadIdx.x;
  if (idx >= 256 * K) return;
  int n = idx / K, k = idx - n * K;
  float v = W[k * 256 + n];
  __nv_bfloat16 hi = __float2bfloat16(v);
  __nv_bfloat16 lo = __float2bfloat16(v - __bfloat162float(hi));
  g_bthi[idx] = hi;
  g_btlo[idx] = lo;
}

// ---------------- tensor-core GEMM + fused attention logits ----------------
__device__ __forceinline__ void mma_bf16(float* c, const uint32_t* a, uint32_t b0, uint32_t b1) {
  asm volatile(
      "mma.sync.aligned.m16n8k16.row.col.f32.bf16.bf16.f32 "
      "{%0,%1,%2,%3}, {%4,%5,%6,%7}, {%8,%9}, {%0,%1,%2,%3};\n"
      : "+f"(c[0]), "+f"(c[1]), "+f"(c[2]), "+f"(c[3])
      : "r"(a[0]), "r"(a[1]), "r"(a[2]), "r"(a[3]), "r"(b0), "r"(b1));
}

__device__ __forceinline__ void ldsm4(uint32_t& r0, uint32_t& r1, uint32_t& r2, uint32_t& r3,
                                      uint32_t addr) {
  asm volatile("ldmatrix.sync.aligned.m8n8.x4.shared.b16 {%0,%1,%2,%3}, [%4];"
               : "=r"(r0), "=r"(r1), "=r"(r2), "=r"(r3) : "r"(addr));
}

#define SSTR 40

__global__ void __launch_bounds__(256, 2)
k_gemm_mma(const float* __restrict__ Ain, int K,
           const float* __restrict__ as_, const float* __restrict__ ad_) {
  const float* A = Ain ? Ain : g_x;
  __shared__ __nv_bfloat16 sAhi[128 * SSTR];
  __shared__ __nv_bfloat16 sAlo[128 * SSTR];
  __shared__ __nv_bfloat16 sBhi[128 * SSTR];
  __shared__ __nv_bfloat16 sBlo[128 * SSTR];

  const int bm = blockIdx.y * 128;
  const int bn = blockIdx.x * 128;
  const int tid = threadIdx.x;
  const int warp = tid >> 5, lane = tid & 31;
  const int wm = warp >> 1, wn = warp & 1;     // 4x2 warp grid
  const int gid = lane >> 2, tig = lane & 3;

  // ldmatrix lane-address components
  const int lt = lane >> 3, lr = lane & 7;
  const int a_row = (lt & 1) * 8 + lr;
  const int a_col = (lt >> 1) * 8;
  const int b_row = (lt >> 1) * 8 + lr;
  const int b_col = (lt & 1) * 8;

  const uint32_t uAhi = (uint32_t)__cvta_generic_to_shared(sAhi);
  const uint32_t uAlo = (uint32_t)__cvta_generic_to_shared(sAlo);
  const uint32_t uBhi = (uint32_t)__cvta_generic_to_shared(sBhi);
  const uint32_t uBlo = (uint32_t)__cvta_generic_to_shared(sBlo);

  float acc[2][8][4];
#pragma unroll
  for (int i = 0; i < 2; i++)
#pragma unroll
    for (int j = 0; j < 8; j++)
#pragma unroll
      for (int q = 0; q < 4; q++) acc[i][j][q] = 0.f;

  for (int k0 = 0; k0 < K; k0 += 32) {
    // --- stage A chunk [128][32] fp32 -> split bf16 hi/lo
#pragma unroll
    for (int it = 0; it < 4; it++) {
      int q = tid + 256 * it;
      int r = q >> 3, c = (q & 7) * 4;
      int gr = bm + r;
      float4 v = make_float4(0.f, 0.f, 0.f, 0.f);
      if (gr < NN) v = *(const float4*)(A + (size_t)gr * K + k0 + c);
      __nv_bfloat16 h0 = __float2bfloat16(v.x), h1 = __float2bfloat16(v.y);
      __nv_bfloat16 h2 = __float2bfloat16(v.z), h3 = __float2bfloat16(v.w);
      __nv_bfloat16 l0 = __float2bfloat16(v.x - __bfloat162float(h0));
      __nv_bfloat16 l1 = __float2bfloat16(v.y - __bfloat162float(h1));
      __nv_bfloat16 l2 = __float2bfloat16(v.z - __bfloat162float(h2));
      __nv_bfloat16 l3 = __float2bfloat16(v.w - __bfloat162float(h3));
      __nv_bfloat162* dh = (__nv_bfloat162*)&sAhi[r * SSTR + c];
      __nv_bfloat162* dl = (__nv_bfloat162*)&sAlo[r * SSTR + c];
      dh[0] = __halves2bfloat162(h0, h1);
      dh[1] = __halves2bfloat162(h2, h3);
      dl[0] = __halves2bfloat162(l0, l1);
      dl[1] = __halves2bfloat162(l2, l3);
    }
    // --- stage B chunk: g_bthi/lo [256][K] -> sB [n(128)][k(32)]
#pragma unroll
    for (int it = 0; it < 2; it++) {
      int q = tid + 256 * it;
      int nl = q >> 2, kq = (q & 3) * 8;
      const uint4* srch = (const uint4*)&g_bthi[(bn + nl) * K + k0 + kq];
      const uint4* srcl = (const uint4*)&g_btlo[(bn + nl) * K + k0 + kq];
      *(uint4*)&sBhi[nl * SSTR + kq] = *srch;
      *(uint4*)&sBlo[nl * SSTR + kq] = *srcl;
    }
    __syncthreads();

#pragma unroll
    for (int ks = 0; ks < 2; ks++) {
      const int kb = ks * 16;
      uint32_t ahi[2][4], alo[2][4];
#pragma unroll
      for (int i = 0; i < 2; i++) {
        uint32_t off = (uint32_t)(((wm * 32 + i * 16 + a_row) * SSTR + kb + a_col) * 2);
        ldsm4(ahi[i][0], ahi[i][1], ahi[i][2], ahi[i][3], uAhi + off);
        ldsm4(alo[i][0], alo[i][1], alo[i][2], alo[i][3], uAlo + off);
      }
#pragma unroll
      for (int jj = 0; jj < 4; jj++) {
        uint32_t off = (uint32_t)(((wn * 64 + jj * 16 + b_row) * SSTR + kb + b_col) * 2);
        uint32_t bh0, bh1, bh2, bh3, bl0, bl1, bl2, bl3;
        ldsm4(bh0, bh1, bh2, bh3, uBhi + off);
        ldsm4(bl0, bl1, bl2, bl3, uBlo + off);
#pragma unroll
        for (int i = 0; i < 2; i++) {
          mma_bf16(acc[i][jj * 2],     ahi[i], bh0, bh1);
          mma_bf16(acc[i][jj * 2],     ahi[i], bl0, bl1);
          mma_bf16(acc[i][jj * 2],     alo[i], bh0, bh1);
          mma_bf16(acc[i][jj * 2 + 1], ahi[i], bh2, bh3);
          mma_bf16(acc[i][jj * 2 + 1], ahi[i], bl2, bl3);
          mma_bf16(acc[i][jj * 2 + 1], alo[i], bh2, bh3);
        }
      }
    }
    __syncthreads();
  }

  // --- epilogue 1: write fp16 h
#pragma unroll
  for (int i = 0; i < 2; i++) {
#pragma unroll
    for (int j = 0; j < 8; j++) {
      int row = bm + wm * 32 + i * 16 + gid;
      int col = bn + wn * 64 + j * 8 + 2 * tig;
      __half2 p01 = __floats2half2_rn(acc[i][j][0], acc[i][j][1]);
      __half2 p23 = __floats2half2_rn(acc[i][j][2], acc[i][j][3]);
      if (row < NN)
        *(__half2*)(g_h16 + (size_t)row * 256 + col) = p01;
      if (row + 8 < NN)
        *(__half2*)(g_h16 + (size_t)(row + 8) * 256 + col) = p23;
    }
  }

  // --- epilogue 2: fused attention logits for head = 2*bn + wn
  {
    const int head = blockIdx.x * 2 + wn;
    float wa[16], wd[16];
#pragma unroll
    for (int j = 0; j < 8; j++) {
      int c = j * 8 + 2 * tig;
      wa[j * 2 + 0] = as_[head * 64 + c];
      wa[j * 2 + 1] = as_[head * 64 + c + 1];
      wd[j * 2 + 0] = ad_[head * 64 + c];
      wd[j * 2 + 1] = ad_[head * 64 + c + 1];
    }
#pragma unroll
    for (int i = 0; i < 2; i++) {
      float s0 = 0.f, s1 = 0.f, d0 = 0.f, d1 = 0.f;
#pragma unroll
      for (int j = 0; j < 8; j++) {
        s0 = fmaf(acc[i][j][0], wa[j * 2], fmaf(acc[i][j][1], wa[j * 2 + 1], s0));
        s1 = fmaf(acc[i][j][2], wa[j * 2], fmaf(acc[i][j][3], wa[j * 2 + 1], s1));
        d0 = fmaf(acc[i][j][0], wd[j * 2], fmaf(acc[i][j][1], wd[j * 2 + 1], d0));
        d1 = fmaf(acc[i][j][2], wd[j * 2], fmaf(acc[i][j][3], wd[j * 2 + 1], d1));
      }
#pragma unroll
      for (int o = 1; o <= 2; o <<= 1) {
        s0 += __shfl_xor_sync(0xffffffffu, s0, o);
        s1 += __shfl_xor_sync(0xffffffffu, s1, o);
        d0 += __shfl_xor_sync(0xffffffffu, d0, o);
        d1 += __shfl_xor_sync(0xffffffffu, d1, o);
      }
      if (tig == 0) {
        int row = bm + wm * 32 + i * 16 + gid;
        if (row < NN)     { g_als[row * 4 + head] = s0; g_ald[row * 4 + head] = d0; }
        if (row + 8 < NN) { g_als[(row + 8) * 4 + head] = s1; g_ald[(row + 8) * 4 + head] = d1; }
      }
    }
  }
}

// ---------------- softmax + aggregation: one warp per dst node ----------------
// Max-shift skipped: logits are O(1) by construction -> exp cannot overflow.
// Per-edge alpha cached in shared memory (gmem fallback for deg > 64).
// Phase B accumulates groups of 4 edges in half2 (HFMA2, full-rate FMA pipe),
// flushing to fp32 once per group: conversion-pipe ops drop ~2.7x per edge.
__device__ __forceinline__ float leaky(float v) { return v >= 0.f ? v : 0.2f * v; }

#define ACAP 64

__global__ void __launch_bounds__(256)
k_agg(const float* __restrict__ bias, float* __restrict__ outp, int do_relu) {
  __shared__ float4 s_alpha[8][ACAP];
  int warp = (blockIdx.x * blockDim.x + threadIdx.x) >> 5;
  int wip = threadIdx.x >> 5;
  int lane = threadIdx.x & 31;
  if (warp >= NN) return;
  float* op = outp ? outp : g_x;
  const int n = warp;
  const int beg = g_offs[n], end = g_offs[n + 1];

  const float4 ald = *(const float4*)&g_ald[n * 4];

  float d0 = 0.f, d1 = 0.f, d2 = 0.f, d3 = 0.f;
  for (int e = beg + lane; e < end; e += 32) {
    int s = g_ssrc[e];
    float4 als = *(const float4*)&g_als[s * 4];
    float p0 = __expf(leaky(als.x + ald.x));
    float p1 = __expf(leaky(als.y + ald.y));
    float p2 = __expf(leaky(als.z + ald.z));
    float p3 = __expf(leaky(als.w + ald.w));
    d0 += p0; d1 += p1; d2 += p2; d3 += p3;
    int idx = e - beg;
    float4 pv = make_float4(p0, p1, p2, p3);
    if (idx < ACAP) s_alpha[wip][idx] = pv;
    else            *(float4*)&g_alpha[(size_t)e * 4] = pv;
  }
#pragma unroll
  for (int o = 16; o; o >>= 1) {
    d0 += __shfl_xor_sync(0xffffffffu, d0, o);
    d1 += __shfl_xor_sync(0xffffffffu, d1, o);
    d2 += __shfl_xor_sync(0xffffffffu, d2, o);
    d3 += __shfl_xor_sync(0xffffffffu, d3, o);
  }
  __syncwarp();

  const bool hs = (lane & 16) != 0;
  const float rA = 1.0f / (hs ? d1 : d0);
  const float rB = 1.0f / (hs ? d3 : d2);

  // phase B: warp-serial over edges (unroll 4); lanes cover 256 feats.
  float4 acc0 = make_float4(0.f, 0.f, 0.f, 0.f);
  float4 acc1 = make_float4(0.f, 0.f, 0.f, 0.f);
  const int deg = end - beg;
  int idx = 0;
  for (; idx + 3 < deg; idx += 4) {
    int s[4]; float4 p[4]; uint2 r0[4], r1[4];
#pragma unroll
    for (int j = 0; j < 4; j++) s[j] = g_ssrc[beg + idx + j];
#pragma unroll
    for (int j = 0; j < 4; j++)
      p[j] = (idx + j < ACAP) ? s_alpha[wip][idx + j]
                              : *(const float4*)&g_alpha[(size_t)(beg + idx + j) * 4];
#pragma unroll
    for (int j = 0; j < 4; j++) {
      const uint2* hp = (const uint2*)(g_h16 + (size_t)s[j] * 256);
      r0[j] = __ldg(hp + lane);
      r1[j] = __ldg(hp + 32 + lane);
    }
    // half2 accumulation over this 4-edge group (|partial| <= ~120 << fp16 max)
    __half2 hc0a = __float2half2_rn(0.f), hc0b = __float2half2_rn(0.f);
    __half2 hc1a = __float2half2_rn(0.f), hc1b = __float2half2_rn(0.f);
#pragma unroll
    for (int j = 0; j < 4; j++) {
      float a0 = (hs ? p[j].y : p[j].x) * rA;
      float a1 = (hs ? p[j].w : p[j].z) * rB;
      __half2 apk = __floats2half2_rn(a0, a1);   // 1 pack per edge
      __half2 ah0 = __low2half2(apk);            // (a0,a0) - ALU broadcast
      __half2 ah1 = __high2half2(apk);           // (a1,a1)
      hc0a = __hfma2(*(const __half2*)&r0[j].x, ah0, hc0a);
      hc0b = __hfma2(*(const __half2*)&r0[j].y, ah0, hc0b);
      hc1a = __hfma2(*(const __half2*)&r1[j].x, ah1, hc1a);
      hc1b = __hfma2(*(const __half2*)&r1[j].y, ah1, hc1b);
    }
    // flush group to fp32 (8 F2F per 4 edges instead of 32)
    float2 f;
    f = __half22float2(hc0a); acc0.x += f.x; acc0.y += f.y;
    f = __half22float2(hc0b); acc0.z += f.x; acc0.w += f.y;
    f = __half22float2(hc1a); acc1.x += f.x; acc1.y += f.y;
    f = __half22float2(hc1b); acc1.z += f.x; acc1.w += f.y;
  }
  for (; idx < deg; ++idx) {
    int s = g_ssrc[beg + idx];
    float4 p = (idx < ACAP) ? s_alpha[wip][idx] : *(const float4*)&g_alpha[(size_t)(beg + idx) * 4];
    float a0 = (hs ? p.y : p.x) * rA;
    float a1 = (hs ? p.w : p.z) * rB;
    const uint2* hp = (const uint2*)(g_h16 + (size_t)s * 256);
    uint2 r0 = __ldg(hp + lane);
    uint2 r1 = __ldg(hp + 32 + lane);
    float2 f;
    f = __half22float2(*(const __half2*)&r0.x); acc0.x = fmaf(f.x, a0, acc0.x); acc0.y = fmaf(f.y, a0, acc0.y);
    f = __half22float2(*(const __half2*)&r0.y); acc0.z = fmaf(f.x, a0, acc0.z); acc0.w = fmaf(f.y, a0, acc0.w);
    f = __half22float2(*(const __half2*)&r1.x); acc1.x = fmaf(f.x, a1, acc1.x); acc1.y = fmaf(f.y, a1, acc1.y);
    f = __half22float2(*(const __half2*)&r1.y); acc1.z = fmaf(f.x, a1, acc1.z); acc1.w = fmaf(f.y, a1, acc1.w);
  }

  float4 t;
  t.x = acc0.x + acc1.x; t.y = acc0.y + acc1.y;
  t.z = acc0.z + acc1.z; t.w = acc0.w + acc1.w;
  t.x += __shfl_xor_sync(0xffffffffu, t.x, 16);
  t.y += __shfl_xor_sync(0xffffffffu, t.y, 16);
  t.z += __shfl_xor_sync(0xffffffffu, t.z, 16);
  t.w += __shfl_xor_sync(0xffffffffu, t.w, 16);
  if (lane < 16) {
    const float4 b4 = *(const float4*)(bias + lane * 4);
    float4 o;
    o.x = t.x * 0.25f + b4.x;
    o.y = t.y * 0.25f + b4.y;
    o.z = t.z * 0.25f + b4.z;
    o.w = t.w * 0.25f + b4.w;
    if (do_relu) {
      o.x = fmaxf(o.x, 0.f); o.y = fmaxf(o.y, 0.f);
      o.z = fmaxf(o.z, 0.f); o.w = fmaxf(o.w, 0.f);
    }
    *(float4*)(op + (size_t)n * 64 + lane * 4) = o;
  }
}

// ---------------- node MLP heads + pooling ----------------
__device__ __forceinline__ float sigmoidf_(float x) { return 1.0f / (1.0f + __expf(-x)); }

__global__ void k_node_mlp(const float* __restrict__ emb, const int* __restrict__ batch,
                           const float* __restrict__ aw1, const float* __restrict__ ab1,
                           const float* __restrict__ aw2, const float* __restrict__ ab2,
                           const float* __restrict__ rw1, const float* __restrict__ rb1,
                           const float* __restrict__ rw2, const float* __restrict__ rb2,
                           const float* __restrict__ cw1, const float* __restrict__ cb1,
                           const float* __restrict__ cw2, const float* __restrict__ cb2,
                           float* __restrict__ anomaly, float* __restrict__ risk,
                           float* __restrict__ resource) {
  int warp = (blockIdx.x * blockDim.x + threadIdx.x) >> 5;
  int lane = threadIdx.x & 31;
  if (warp >= NN) return;
  int n = warp;
  float e0 = emb[(size_t)n * 64 + lane];
  float e1 = emb[(size_t)n * 64 + 32 + lane];

  float ha = ab1[lane], hr = rb1[lane], hc = cb1[lane];
#pragma unroll
  for (int k = 0; k < 32; k++) {
    float ek = __shfl_sync(0xffffffffu, e0, k);
    ha = fmaf(ek, aw1[k * 32 + lane], ha);
    hr = fmaf(ek, rw1[k * 32 + lane], hr);
    hc = fmaf(ek, cw1[k * 32 + lane], hc);
  }
#pragma unroll
  for (int k = 0; k < 32; k++) {
    float ek = __shfl_sync(0xffffffffu, e1, k);
    ha = fmaf(ek, aw1[(k + 32) * 32 + lane], ha);
    hr = fmaf(ek, rw1[(k + 32) * 32 + lane], hr);
    hc = fmaf(ek, cw1[(k + 32) * 32 + lane], hc);
  }
  ha = fmaxf(ha, 0.f); hr = fmaxf(hr, 0.f); hc = fmaxf(hc, 0.f);

  float va = ha * aw2[lane];
  float vr = hr * rw2[lane];
#pragma unroll
  for (int o = 16; o; o >>= 1) {
    va += __shfl_xor_sync(0xffffffffu, va, o);
    vr += __shfl_xor_sync(0xffffffffu, vr, o);
  }
  if (lane == 0) {
    anomaly[n] = sigmoidf_(va + ab2[0]);
    risk[n]    = sigmoidf_(vr + rb2[0]);
  }
#pragma unroll
  for (int o5 = 0; o5 < 5; o5++) {
    float vc = hc * cw2[lane * 5 + o5];
#pragma unroll
    for (int o = 16; o; o >>= 1) vc += __shfl_xor_sync(0xffffffffu, vc, o);
    if (lane == 0) resource[(size_t)n * 5 + o5] = vc + cb2[o5];
  }

  int g = batch[n];
  atomicAdd(&g_psum[g * 64 + lane], e0);
  atomicAdd(&g_psum[g * 64 + 32 + lane], e1);
  if (lane == 0) atomicAdd(&g_pcnt[g], 1.0f);
}

__global__ void k_graph_head(const float* __restrict__ gw1, const float* __restrict__ gb1,
                             const float* __restrict__ gw2, const float* __restrict__ gb2,
                             float* __restrict__ glog) {
  int g = blockIdx.x;
  int lane = threadIdx.x;
  float rc = 1.0f / fmaxf(g_pcnt[g], 1.0f);
  float hid = gb1[lane];
#pragma unroll
  for (int c = 0; c < 64; c++)
    hid = fmaf(g_psum[g * 64 + c] * rc, gw1[c * 32 + lane], hid);
  hid = fmaxf(hid, 0.f);
#pragma unroll
  for (int o4 = 0; o4 < 4; o4++) {
    float v = hid * gw2[lane * 4 + o4];
#pragma unroll
    for (int o = 16; o; o >>= 1) v += __shfl_xor_sync(0xffffffffu, v, o);
    if (lane == 0) glog[g * 4 + o4] = v + gb2[o4];
  }
}

// ---------------- launch ----------------
extern "C" void kernel_launch(void* const* d_in, const int* in_sizes, int n_in,
                              void* d_out, int out_size) {
  const float* x    = (const float*)d_in[0];
  const int*   ei   = (const int*)d_in[1];
  const int*   batch= (const int*)d_in[2];
  const float* W1   = (const float*)d_in[3];
  const float* as1  = (const float*)d_in[4];
  const float* ad1  = (const float*)d_in[5];
  const float* b1   = (const float*)d_in[6];
  const float* W2   = (const float*)d_in[7];
  const float* as2  = (const float*)d_in[8];
  const float* ad2  = (const float*)d_in[9];
  const float* b2   = (const float*)d_in[10];
  const float* W3   = (const float*)d_in[11];
  const float* as3  = (const float*)d_in[12];
  const float* ad3  = (const float*)d_in[13];
  const float* b3   = (const float*)d_in[14];
  const float* aw1  = (const float*)d_in[15];
  const float* ab1  = (const float*)d_in[16];
  const float* aw2  = (const float*)d_in[17];
  const float* ab2  = (const float*)d_in[18];
  const float* rw1  = (const float*)d_in[19];
  const float* rb1  = (const float*)d_in[20];
  const float* rw2  = (const float*)d_in[21];
  const float* rb2  = (const float*)d_in[22];
  const float* cw1  = (const float*)d_in[23];
  const float* cb1  = (const float*)d_in[24];
  const float* cw2  = (const float*)d_in[25];
  const float* cb2  = (const float*)d_in[26];
  const float* gw1  = (const float*)d_in[27];
  const float* gb1  = (const float*)d_in[28];
  const float* gw2  = (const float*)d_in[29];
  const float* gb2  = (const float*)d_in[30];

  float* out      = (float*)d_out;
  float* emb      = out;                        // N*64
  float* anomaly  = out + (size_t)NN * 64;      // N
  float* risk     = anomaly + NN;               // N
  float* resource = risk + NN;                  // N*5
  float* glog     = resource + (size_t)NN * 5;  // G*4

  dim3 gg(2, (NN + 127) / 128);
  int agg_grid = (NN * 32 + 255) / 256;

  k_init<<<(NN + 255) / 256, 256>>>();
  k_degree<<<(NE / 2 + 255) / 256, 256>>>(ei);
  k_bsplit<<<(256 * 128 + 255) / 256, 256>>>(W1, 128);
  k_gemm_mma<<<gg, 256>>>(x, 128, as1, ad1);
  k_scan1<<<SCB, 256>>>();
  k_scan2<<<1, 256>>>();
  k_scan3<<<SCB, 256>>>();
  k_scatter<<<(NE2 + 255) / 256, 256>>>(ei);
  k_agg<<<agg_grid, 256>>>(b1, nullptr, 1);

  // layer 2 (K=64)
  k_bsplit<<<(256 * 64 + 255) / 256, 256>>>(W2, 64);
  k_gemm_mma<<<gg, 256>>>(nullptr, 64, as2, ad2);
  k_agg<<<agg_grid, 256>>>(b2, nullptr, 1);
  // layer 3 (K=64)
  k_bsplit<<<(256 * 64 + 255) / 256, 256>>>(W3, 64);
  k_gemm_mma<<<gg, 256>>>(nullptr, 64, as3, ad3);
  k_agg<<<agg_grid, 256>>>(b3, emb, 0);

  // heads
  k_node_mlp<<<agg_grid, 256>>>(emb, batch, aw1, ab1, aw2, ab2,
                                rw1, rb1, rw2, rb2, cw1, cb1, cw2, cb2,
                                anomaly, risk, resource);
  k_graph_head<<<NG, 32>>>(gw1, gb1, gw2, gb2, glog);
}

// round 17
// speedup vs baseline: 1.4064x; 1.0445x over previous
#include <cuda_runtime.h>
#include <cuda_fp16.h>
#include <cstdint>

#define NN 50000
#define NE 800000
#define NE2 850000   /* NE + NN self loops */
#define NG 64
#define SCB 196      /* scan blocks: 196*256 >= NN */

// ---------------- device scratch (no allocations allowed) ----------------
__device__ __align__(16) __half g_h16[NN * 256]; // per-layer h = x@W  [N, H*C] fp16
__device__ __align__(16) __half g_x16[NN * 64]; // layer activation buffer fp16
__device__ __align__(16) float g_als[NN * 4];
__device__ __align__(16) float g_ald[NN * 4];
__device__ __align__(16) float g_alpha[NE2 * 4]; // overflow fallback only
__device__ __align__(16) __half g_bthi[256 * 128]; // W^T split hi [n][k] fp16
__device__ __align__(16) __half g_btlo[256 * 128]; // W^T split lo (subnormal ok)
__device__ int   g_deg[NN];
__device__ int   g_offs[NN + 1];
__device__ int   g_cursor[NN];
__device__ int   g_ssrc[NE2];
__device__ int   g_bsum[256];
__device__ int   g_boff[256];
__device__ float g_psum[NG * 64];
__device__ float g_pcnt[NG];

// ---------------- CSR build ----------------
__global__ void k_init() {
  int i = blockIdx.x * blockDim.x + threadIdx.x;
  if (i < NN) g_deg[i] = 0;              // self-loop added analytically in scan
  if (i < NG * 64) g_psum[i] = 0.f;
  if (i < NG) g_pcnt[i] = 0.f;
}

__global__ void k_degree(const int* __restrict__ ei) {
  int t = blockIdx.x * blockDim.x + threadIdx.x;
  int e = t * 2;
  if (e + 1 < NE) {
    int2 d2 = *(const int2*)(ei + NE + e);
    atomicAdd(&g_deg[d2.x], 1);
    atomicAdd(&g_deg[d2.y], 1);
  } else if (e < NE) {
    atomicAdd(&g_deg[ei[NE + e]], 1);
  }
}

// scan phase 1: per-block sums of (deg+1)
__global__ void k_scan1() {
  __shared__ int ssum[8];
  int t = threadIdx.x;
  int i = blockIdx.x * 256 + t;
  int v = (i < NN) ? g_deg[i] + 1 : 0;
#pragma unroll
  for (int o = 16; o; o >>= 1) v += __shfl_xor_sync(0xffffffffu, v, o);
  if ((t & 31) == 0) ssum[t >> 5] = v;
  __syncthreads();
  if (t == 0) {
    int s = 0;
#pragma unroll
    for (int w = 0; w < 8; w++) s += ssum[w];
    g_bsum[blockIdx.x] = s;
  }
}

// scan phase 2: exclusive scan of block sums (single small block)
__global__ void k_scan2() {
  __shared__ int s[256];
  int t = threadIdx.x;
  int v = (t < SCB) ? g_bsum[t] : 0;
  s[t] = v;
  __syncthreads();
#pragma unroll
  for (int off = 1; off < 256; off <<= 1) {
    int u = (t >= off) ? s[t - off] : 0;
    __syncthreads();
    s[t] += u;
    __syncthreads();
  }
  if (t < SCB) g_boff[t] = s[t] - v;    // exclusive
  if (t == 0) g_offs[NN] = s[255];      // total = NE2
}

// scan phase 3: intra-block scan + write offsets/cursor
__global__ void k_scan3() {
  __shared__ int s[256];
  int t = threadIdx.x;
  int i = blockIdx.x * 256 + t;
  int v = (i < NN) ? g_deg[i] + 1 : 0;
  s[t] = v;
  __syncthreads();
#pragma unroll
  for (int off = 1; off < 256; off <<= 1) {
    int u = (t >= off) ? s[t - off] : 0;
    __syncthreads();
    s[t] += u;
    __syncthreads();
  }
  if (i < NN) {
    int off = g_boff[blockIdx.x] + s[t] - v;
    g_offs[i] = off;
    g_cursor[i] = off;
  }
}

__global__ void k_scatter(const int* __restrict__ ei) {
  int e = blockIdx.x * blockDim.x + threadIdx.x;
  if (e >= NE2) return;
  int s, d;
  if (e < NE) { s = ei[e]; d = ei[NE + e]; }
  else        { s = e - NE; d = s; }
  int pos = atomicAdd(&g_cursor[d], 1);
  g_ssrc[pos] = s;
}

// ---------------- W split+transpose: W[K][256] fp32 -> g_bthi/lo [256][K] fp16 ----
// lo = w - fp16(w) lands in fp16 subnormal range; HMMA handles subnormals.
__global__ void k_bsplit(const float* __restrict__ W, int K) {
  int idx = blockIdx.x * blockDim.x + threadIdx.x;
  if (idx >= 256 * K) return;
  int n = idx / K, k = idx - n * K;
  float v = W[k * 256 + n];
  __half hi = __float2half_rn(v);
  __half lo = __float2half_rn(v - __half2float(hi));
  g_bthi[idx] = hi;
  g_btlo[idx] = lo;
}

// ---------------- tensor-core GEMM + fused attention logits ----------------
// h = A@(Bhi+Blo): A plain fp16 (error ~2^-12, same order as fp16 h storage),
// B split fp16 hi/lo -> 2 MMAs per tile, single A buffer, single accumulator.
__device__ __forceinline__ void mma_f16(float* c, const uint32_t* a, uint32_t b0, uint32_t b1) {
  asm volatile(
      "mma.sync.aligned.m16n8k16.row.col.f32.f16.f16.f32 "
      "{%0,%1,%2,%3}, {%4,%5,%6,%7}, {%8,%9}, {%0,%1,%2,%3};\n"
      : "+f"(c[0]), "+f"(c[1]), "+f"(c[2]), "+f"(c[3])
      : "r"(a[0]), "r"(a[1]), "r"(a[2]), "r"(a[3]), "r"(b0), "r"(b1));
}

__device__ __forceinline__ void ldsm4(uint32_t& r0, uint32_t& r1, uint32_t& r2, uint32_t& r3,
                                      uint32_t addr) {
  asm volatile("ldmatrix.sync.aligned.m8n8.x4.shared.b16 {%0,%1,%2,%3}, [%4];"
               : "=r"(r0), "=r"(r1), "=r"(r2), "=r"(r3) : "r"(addr));
}

#define SSTR 40

__global__ void __launch_bounds__(256, 2)
k_gemm_mma(const float* __restrict__ Ain, int K,
           const float* __restrict__ as_, const float* __restrict__ ad_) {
  __shared__ __half sA[128 * SSTR];
  __shared__ __half sBhi[128 * SSTR];
  __shared__ __half sBlo[128 * SSTR];

  const int bm = blockIdx.y * 128;
  const int bn = blockIdx.x * 128;
  const int tid = threadIdx.x;
  const int warp = tid >> 5, lane = tid & 31;
  const int wm = warp >> 1, wn = warp & 1;     // 4x2 warp grid
  const int gid = lane >> 2, tig = lane & 3;

  // ldmatrix lane-address components
  const int lt = lane >> 3, lr = lane & 7;
  const int a_row = (lt & 1) * 8 + lr;
  const int a_col = (lt >> 1) * 8;
  const int b_row = (lt >> 1) * 8 + lr;
  const int b_col = (lt & 1) * 8;

  const uint32_t uA   = (uint32_t)__cvta_generic_to_shared(sA);
  const uint32_t uBhi = (uint32_t)__cvta_generic_to_shared(sBhi);
  const uint32_t uBlo = (uint32_t)__cvta_generic_to_shared(sBlo);

  float acc[2][8][4];
#pragma unroll
  for (int i = 0; i < 2; i++)
#pragma unroll
    for (int j = 0; j < 8; j++)
#pragma unroll
      for (int q = 0; q < 4; q++) acc[i][j][q] = 0.f;

  for (int k0 = 0; k0 < K; k0 += 32) {
    // --- stage A chunk [128][32] -> fp16 (layer1 cvt from fp32; else copy fp16)
#pragma unroll
    for (int it = 0; it < 4; it++) {
      int q = tid + 256 * it;
      int r = q >> 3, c = (q & 7) * 4;
      int gr = bm + r;
      uint2 pk = make_uint2(0u, 0u);
      if (Ain) {
        float4 v = make_float4(0.f, 0.f, 0.f, 0.f);
        if (gr < NN) v = *(const float4*)(Ain + (size_t)gr * K + k0 + c);
        *(__half2*)&pk.x = __floats2half2_rn(v.x, v.y);
        *(__half2*)&pk.y = __floats2half2_rn(v.z, v.w);
      } else {
        if (gr < NN) pk = *(const uint2*)(g_x16 + (size_t)gr * K + k0 + c);
      }
      *(uint2*)&sA[r * SSTR + c] = pk;
    }
    // --- stage B chunk: g_bthi/lo [256][K] -> sB [n(128)][k(32)]
#pragma unroll
    for (int it = 0; it < 2; it++) {
      int q = tid + 256 * it;
      int nl = q >> 2, kq = (q & 3) * 8;
      const uint4* srch = (const uint4*)&g_bthi[(bn + nl) * K + k0 + kq];
      const uint4* srcl = (const uint4*)&g_btlo[(bn + nl) * K + k0 + kq];
      *(uint4*)&sBhi[nl * SSTR + kq] = *srch;
      *(uint4*)&sBlo[nl * SSTR + kq] = *srcl;
    }
    __syncthreads();

#pragma unroll
    for (int ks = 0; ks < 2; ks++) {
      const int kb = ks * 16;
      uint32_t a[2][4];
#pragma unroll
      for (int i = 0; i < 2; i++) {
        uint32_t off = (uint32_t)(((wm * 32 + i * 16 + a_row) * SSTR + kb + a_col) * 2);
        ldsm4(a[i][0], a[i][1], a[i][2], a[i][3], uA + off);
      }
#pragma unroll
      for (int jj = 0; jj < 4; jj++) {
        uint32_t off = (uint32_t)(((wn * 64 + jj * 16 + b_row) * SSTR + kb + b_col) * 2);
        uint32_t bh0, bh1, bh2, bh3, bl0, bl1, bl2, bl3;
        ldsm4(bh0, bh1, bh2, bh3, uBhi + off);
        ldsm4(bl0, bl1, bl2, bl3, uBlo + off);
#pragma unroll
        for (int i = 0; i < 2; i++) {
          mma_f16(acc[i][jj * 2],     a[i], bh0, bh1);
          mma_f16(acc[i][jj * 2],     a[i], bl0, bl1);
          mma_f16(acc[i][jj * 2 + 1], a[i], bh2, bh3);
          mma_f16(acc[i][jj * 2 + 1], a[i], bl2, bl3);
        }
      }
    }
    __syncthreads();
  }

  // --- epilogue 1: write fp16 h
#pragma unroll
  for (int i = 0; i < 2; i++) {
#pragma unroll
    for (int j = 0; j < 8; j++) {
      int row = bm + wm * 32 + i * 16 + gid;
      int col = bn + wn * 64 + j * 8 + 2 * tig;
      __half2 p01 = __floats2half2_rn(acc[i][j][0], acc[i][j][1]);
      __half2 p23 = __floats2half2_rn(acc[i][j][2], acc[i][j][3]);
      if (row < NN)
        *(__half2*)(g_h16 + (size_t)row * 256 + col) = p01;
      if (row + 8 < NN)
        *(__half2*)(g_h16 + (size_t)(row + 8) * 256 + col) = p23;
    }
  }

  // --- epilogue 2: fused attention logits for head = 2*bn + wn
  {
    const int head = blockIdx.x * 2 + wn;
    float wa[16], wd[16];
#pragma unroll
    for (int j = 0; j < 8; j++) {
      int c = j * 8 + 2 * tig;
      wa[j * 2 + 0] = as_[head * 64 + c];
      wa[j * 2 + 1] = as_[head * 64 + c + 1];
      wd[j * 2 + 0] = ad_[head * 64 + c];
      wd[j * 2 + 1] = ad_[head * 64 + c + 1];
    }
#pragma unroll
    for (int i = 0; i < 2; i++) {
      float s0 = 0.f, s1 = 0.f, d0 = 0.f, d1 = 0.f;
#pragma unroll
      for (int j = 0; j < 8; j++) {
        s0 = fmaf(acc[i][j][0], wa[j * 2], fmaf(acc[i][j][1], wa[j * 2 + 1], s0));
        s1 = fmaf(acc[i][j][2], wa[j * 2], fmaf(acc[i][j][3], wa[j * 2 + 1], s1));
        d0 = fmaf(acc[i][j][0], wd[j * 2], fmaf(acc[i][j][1], wd[j * 2 + 1], d0));
        d1 = fmaf(acc[i][j][2], wd[j * 2], fmaf(acc[i][j][3], wd[j * 2 + 1], d1));
      }
#pragma unroll
      for (int o = 1; o <= 2; o <<= 1) {
        s0 += __shfl_xor_sync(0xffffffffu, s0, o);
        s1 += __shfl_xor_sync(0xffffffffu, s1, o);
        d0 += __shfl_xor_sync(0xffffffffu, d0, o);
        d1 += __shfl_xor_sync(0xffffffffu, d1, o);
      }
      if (tig == 0) {
        int row = bm + wm * 32 + i * 16 + gid;
        if (row < NN)     { g_als[row * 4 + head] = s0; g_ald[row * 4 + head] = d0; }
        if (row + 8 < NN) { g_als[(row + 8) * 4 + head] = s1; g_ald[(row + 8) * 4 + head] = d1; }
      }
    }
  }
}

// ---------------- softmax + aggregation: one warp per dst node ----------------
// Max-shift skipped: logits are O(1) by construction -> exp cannot overflow.
// Per-edge alpha cached in shared memory (gmem fallback for deg > 64).
// Phase B accumulates groups of 4 edges in half2 (HFMA2, full-rate FMA pipe).
__device__ __forceinline__ float leaky(float v) { return v >= 0.f ? v : 0.2f * v; }

#define ACAP 64

__global__ void __launch_bounds__(256)
k_agg(const float* __restrict__ bias, float* __restrict__ outp, int do_relu) {
  __shared__ float4 s_alpha[8][ACAP];
  int warp = (blockIdx.x * blockDim.x + threadIdx.x) >> 5;
  int wip = threadIdx.x >> 5;
  int lane = threadIdx.x & 31;
  if (warp >= NN) return;
  const int n = warp;
  const int beg = g_offs[n], end = g_offs[n + 1];

  const float4 ald = *(const float4*)&g_ald[n * 4];

  float d0 = 0.f, d1 = 0.f, d2 = 0.f, d3 = 0.f;
  for (int e = beg + lane; e < end; e += 32) {
    int s = g_ssrc[e];
    float4 als = *(const float4*)&g_als[s * 4];
    float p0 = __expf(leaky(als.x + ald.x));
    float p1 = __expf(leaky(als.y + ald.y));
    float p2 = __expf(leaky(als.z + ald.z));
    float p3 = __expf(leaky(als.w + ald.w));
    d0 += p0; d1 += p1; d2 += p2; d3 += p3;
    int idx = e - beg;
    float4 pv = make_float4(p0, p1, p2, p3);
    if (idx < ACAP) s_alpha[wip][idx] = pv;
    else            *(float4*)&g_alpha[(size_t)e * 4] = pv;
  }
#pragma unroll
  for (int o = 16; o; o >>= 1) {
    d0 += __shfl_xor_sync(0xffffffffu, d0, o);
    d1 += __shfl_xor_sync(0xffffffffu, d1, o);
    d2 += __shfl_xor_sync(0xffffffffu, d2, o);
    d3 += __shfl_xor_sync(0xffffffffu, d3, o);
  }
  __syncwarp();

  const bool hs = (lane & 16) != 0;
  const float rA = 1.0f / (hs ? d1 : d0);
  const float rB = 1.0f / (hs ? d3 : d2);

  float4 acc0 = make_float4(0.f, 0.f, 0.f, 0.f);
  float4 acc1 = make_float4(0.f, 0.f, 0.f, 0.f);
  const int deg = end - beg;
  int idx = 0;
  for (; idx + 3 < deg; idx += 4) {
    int s[4]; float4 p[4]; uint2 r0[4], r1[4];
#pragma unroll
    for (int j = 0; j < 4; j++) s[j] = g_ssrc[beg + idx + j];
#pragma unroll
    for (int j = 0; j < 4; j++)
      p[j] = (idx + j < ACAP) ? s_alpha[wip][idx + j]
                              : *(const float4*)&g_alpha[(size_t)(beg + idx + j) * 4];
#pragma unroll
    for (int j = 0; j < 4; j++) {
      const uint2* hp = (const uint2*)(g_h16 + (size_t)s[j] * 256);
      r0[j] = __ldg(hp + lane);
      r1[j] = __ldg(hp + 32 + lane);
    }
    __half2 hc0a = __float2half2_rn(0.f), hc0b = __float2half2_rn(0.f);
    __half2 hc1a = __float2half2_rn(0.f), hc1b = __float2half2_rn(0.f);
#pragma unroll
    for (int j = 0; j < 4; j++) {
      float a0 = (hs ? p[j].y : p[j].x) * rA;
      float a1 = (hs ? p[j].w : p[j].z) * rB;
      __half2 apk = __floats2half2_rn(a0, a1);
      __half2 ah0 = __low2half2(apk);
      __half2 ah1 = __high2half2(apk);
      hc0a = __hfma2(*(const __half2*)&r0[j].x, ah0, hc0a);
      hc0b = __hfma2(*(const __half2*)&r0[j].y, ah0, hc0b);
      hc1a = __hfma2(*(const __half2*)&r1[j].x, ah1, hc1a);
      hc1b = __hfma2(*(const __half2*)&r1[j].y, ah1, hc1b);
    }
    float2 f;
    f = __half22float2(hc0a); acc0.x += f.x; acc0.y += f.y;
    f = __half22float2(hc0b); acc0.z += f.x; acc0.w += f.y;
    f = __half22float2(hc1a); acc1.x += f.x; acc1.y += f.y;
    f = __half22float2(hc1b); acc1.z += f.x; acc1.w += f.y;
  }
  for (; idx < deg; ++idx) {
    int s = g_ssrc[beg + idx];
    float4 p = (idx < ACAP) ? s_alpha[wip][idx] : *(const float4*)&g_alpha[(size_t)(beg + idx) * 4];
    float a0 = (hs ? p.y : p.x) * rA;
    float a1 = (hs ? p.w : p.z) * rB;
    const uint2* hp = (const uint2*)(g_h16 + (size_t)s * 256);
    uint2 r0 = __ldg(hp + lane);
    uint2 r1 = __ldg(hp + 32 + lane);
    float2 f;
    f = __half22float2(*(const __half2*)&r0.x); acc0.x = fmaf(f.x, a0, acc0.x); acc0.y = fmaf(f.y, a0, acc0.y);
    f = __half22float2(*(const __half2*)&r0.y); acc0.z = fmaf(f.x, a0, acc0.z); acc0.w = fmaf(f.y, a0, acc0.w);
    f = __half22float2(*(const __half2*)&r1.x); acc1.x = fmaf(f.x, a1, acc1.x); acc1.y = fmaf(f.y, a1, acc1.y);
    f = __half22float2(*(const __half2*)&r1.y); acc1.z = fmaf(f.x, a1, acc1.z); acc1.w = fmaf(f.y, a1, acc1.w);
  }

  float4 t;
  t.x = acc0.x + acc1.x; t.y = acc0.y + acc1.y;
  t.z = acc0.z + acc1.z; t.w = acc0.w + acc1.w;
  t.x += __shfl_xor_sync(0xffffffffu, t.x, 16);
  t.y += __shfl_xor_sync(0xffffffffu, t.y, 16);
  t.z += __shfl_xor_sync(0xffffffffu, t.z, 16);
  t.w += __shfl_xor_sync(0xffffffffu, t.w, 16);
  if (lane < 16) {
    const float4 b4 = *(const float4*)(bias + lane * 4);
    float ox = t.x * 0.25f + b4.x;
    float oy = t.y * 0.25f + b4.y;
    float oz = t.z * 0.25f + b4.z;
    float ow = t.w * 0.25f + b4.w;
    if (outp) {
      *(float4*)(outp + (size_t)n * 64 + lane * 4) = make_float4(ox, oy, oz, ow);
    } else {
      ox = fmaxf(ox, 0.f); oy = fmaxf(oy, 0.f);
      oz = fmaxf(oz, 0.f); ow = fmaxf(ow, 0.f);
      uint2 pk;
      *(__half2*)&pk.x = __floats2half2_rn(ox, oy);
      *(__half2*)&pk.y = __floats2half2_rn(oz, ow);
      *(uint2*)(g_x16 + (size_t)n * 64 + lane * 4) = pk;
    }
  }
}

// ---------------- node MLP heads + pooling ----------------
__device__ __forceinline__ float sigmoidf_(float x) { return 1.0f / (1.0f + __expf(-x)); }

__global__ void k_node_mlp(const float* __restrict__ emb, const int* __restrict__ batch,
                           const float* __restrict__ aw1, const float* __restrict__ ab1,
                           const float* __restrict__ aw2, const float* __restrict__ ab2,
                           const float* __restrict__ rw1, const float* __restrict__ rb1,
                           const float* __restrict__ rw2, const float* __restrict__ rb2,
                           const float* __restrict__ cw1, const float* __restrict__ cb1,
                           const float* __restrict__ cw2, const float* __restrict__ cb2,
                           float* __restrict__ anomaly, float* __restrict__ risk,
                           float* __restrict__ resource) {
  int warp = (blockIdx.x * blockDim.x + threadIdx.x) >> 5;
  int lane = threadIdx.x & 31;
  if (warp >= NN) return;
  int n = warp;
  float e0 = emb[(size_t)n * 64 + lane];
  float e1 = emb[(size_t)n * 64 + 32 + lane];

  float ha = ab1[lane], hr = rb1[lane], hc = cb1[lane];
#pragma unroll
  for (int k = 0; k < 32; k++) {
    float ek = __shfl_sync(0xffffffffu, e0, k);
    ha = fmaf(ek, aw1[k * 32 + lane], ha);
    hr = fmaf(ek, rw1[k * 32 + lane], hr);
    hc = fmaf(ek, cw1[k * 32 + lane], hc);
  }
#pragma unroll
  for (int k = 0; k < 32; k++) {
    float ek = __shfl_sync(0xffffffffu, e1, k);
    ha = fmaf(ek, aw1[(k + 32) * 32 + lane], ha);
    hr = fmaf(ek, rw1[(k + 32) * 32 + lane], hr);
    hc = fmaf(ek, cw1[(k + 32) * 32 + lane], hc);
  }
  ha = fmaxf(ha, 0.f); hr = fmaxf(hr, 0.f); hc = fmaxf(hc, 0.f);

  float va = ha * aw2[lane];
  float vr = hr * rw2[lane];
#pragma unroll
  for (int o = 16; o; o >>= 1) {
    va += __shfl_xor_sync(0xffffffffu, va, o);
    vr += __shfl_xor_sync(0xffffffffu, vr, o);
  }
  if (lane == 0) {
    anomaly[n] = sigmoidf_(va + ab2[0]);
    risk[n]    = sigmoidf_(vr + rb2[0]);
  }
#pragma unroll
  for (int o5 = 0; o5 < 5; o5++) {
    float vc = hc * cw2[lane * 5 + o5];
#pragma unroll
    for (int o = 16; o; o >>= 1) vc += __shfl_xor_sync(0xffffffffu, vc, o);
    if (lane == 0) resource[(size_t)n * 5 + o5] = vc + cb2[o5];
  }

  int g = batch[n];
  atomicAdd(&g_psum[g * 64 + lane], e0);
  atomicAdd(&g_psum[g * 64 + 32 + lane], e1);
  if (lane == 0) atomicAdd(&g_pcnt[g], 1.0f);
}

__global__ void k_graph_head(const float* __restrict__ gw1, const float* __restrict__ gb1,
                             const float* __restrict__ gw2, const float* __restrict__ gb2,
                             float* __restrict__ glog) {
  int g = blockIdx.x;
  int lane = threadIdx.x;
  float rc = 1.0f / fmaxf(g_pcnt[g], 1.0f);
  float hid = gb1[lane];
#pragma unroll
  for (int c = 0; c < 64; c++)
    hid = fmaf(g_psum[g * 64 + c] * rc, gw1[c * 32 + lane], hid);
  hid = fmaxf(hid, 0.f);
#pragma unroll
  for (int o4 = 0; o4 < 4; o4++) {
    float v = hid * gw2[lane * 4 + o4];
#pragma unroll
    for (int o = 16; o; o >>= 1) v += __shfl_xor_sync(0xffffffffu, v, o);
    if (lane == 0) glog[g * 4 + o4] = v + gb2[o4];
  }
}

// ---------------- launch ----------------
extern "C" void kernel_launch(void* const* d_in, const int* in_sizes, int n_in,
                              void* d_out, int out_size) {
  const float* x    = (const float*)d_in[0];
  const int*   ei   = (const int*)d_in[1];
  const int*   batch= (const int*)d_in[2];
  const float* W1   = (const float*)d_in[3];
  const float* as1  = (const float*)d_in[4];
  const float* ad1  = (const float*)d_in[5];
  const float* b1   = (const float*)d_in[6];
  const float* W2   = (const float*)d_in[7];
  const float* as2  = (const float*)d_in[8];
  const float* ad2  = (const float*)d_in[9];
  const float* b2   = (const float*)d_in[10];
  const float* W3   = (const float*)d_in[11];
  const float* as3  = (const float*)d_in[12];
  const float* ad3  = (const float*)d_in[13];
  const float* b3   = (const float*)d_in[14];
  const float* aw1  = (const float*)d_in[15];
  const float* ab1  = (const float*)d_in[16];
  const float* aw2  = (const float*)d_in[17];
  const float* ab2  = (const float*)d_in[18];
  const float* rw1  = (const float*)d_in[19];
  const float* rb1  = (const float*)d_in[20];
  const float* rw2  = (const float*)d_in[21];
  const float* rb2  = (const float*)d_in[22];
  const float* cw1  = (const float*)d_in[23];
  const float* cb1  = (const float*)d_in[24];
  const float* cw2  = (const float*)d_in[25];
  const float* cb2  = (const float*)d_in[26];
  const float* gw1  = (const float*)d_in[27];
  const float* gb1  = (const float*)d_in[28];
  const float* gw2  = (const float*)d_in[29];
  const float* gb2  = (const float*)d_in[30];

  float* out      = (float*)d_out;
  float* emb      = out;                        // N*64
  float* anomaly  = out + (size_t)NN * 64;      // N
  float* risk     = anomaly + NN;               // N
  float* resource = risk + NN;                  // N*5
  float* glog     = resource + (size_t)NN * 5;  // G*4

  dim3 gg(2, (NN + 127) / 128);
  int agg_grid = (NN * 32 + 255) / 256;

  k_init<<<(NN + 255) / 256, 256>>>();
  k_degree<<<(NE / 2 + 255) / 256, 256>>>(ei);
  k_bsplit<<<(256 * 128 + 255) / 256, 256>>>(W1, 128);
  k_gemm_mma<<<gg, 256>>>(x, 128, as1, ad1);
  k_scan1<<<SCB, 256>>>();
  k_scan2<<<1, 256>>>();
  k_scan3<<<SCB, 256>>>();
  k_scatter<<<(NE2 + 255) / 256, 256>>>(ei);
  k_agg<<<agg_grid, 256>>>(b1, nullptr, 1);

  // layer 2 (K=64)
  k_bsplit<<<(256 * 64 + 255) / 256, 256>>>(W2, 64);
  k_gemm_mma<<<gg, 256>>>(nullptr, 64, as2, ad2);
  k_agg<<<agg_grid, 256>>>(b2, nullptr, 1);
  // layer 3 (K=64)
  k_bsplit<<<(256 * 64 + 255) / 256, 256>>>(W3, 64);
  k_gemm_mma<<<gg, 256>>>(nullptr, 64, as3, ad3);
  k_agg<<<agg_grid, 256>>>(b3, emb, 0);

  // heads
  k_node_mlp<<<agg_grid, 256>>>(emb, batch, aw1, ab1, aw2, ab2,
                                rw1, rb1, rw2, rb2, cw1, cb1, cw2, cb2,
                                anomaly, risk, resource);
  k_graph_head<<<NG, 32>>>(gw1, gb1, gw2, gb2, glog);
}